// round 5
// baseline (speedup 1.0000x reference)
#include <cuda_runtime.h>
#include <cstdint>

#define SQ 2048
#define DH 64
#define NBH 24
#define NTILE 16
#define MASKF (-1.0e9f)
#define SCL 0.5f

typedef unsigned long long ull;

// mask dtype flag: 0 = 1-byte bool/uint8, 1 = int32, 2 = float32
__device__ int g_mask_dtype;
// per-(row, 128-col tile) partial softmax stats (m_i, s_i)
__device__ float2 g_MS[(size_t)NBH * SQ * NTILE];
// per-(row, tile) rescale factor f = exp(m_i - M) / S
__device__ float g_F[(size_t)NBH * SQ * NTILE];

// ---- packed f32x2 helpers ----
__device__ __forceinline__ ull pk2(float x) {
    ull r; asm("mov.b64 %0, {%1, %1};" : "=l"(r) : "f"(x)); return r;
}
__device__ __forceinline__ void fma2(ull& d, ull a, ull b) {
    asm("fma.rn.f32x2 %0, %1, %2, %0;" : "+l"(d) : "l"(a), "l"(b));
}
__device__ __forceinline__ float2 unpk(ull v) {
    float2 r; asm("mov.b64 {%0, %1}, %2;" : "=f"(r.x), "=f"(r.y) : "l"(v)); return r;
}
// ---- cp.async helpers ----
__device__ __forceinline__ void cpasync16(const void* smem_dst, const void* gmem_src) {
    uint32_t d = (uint32_t)__cvta_generic_to_shared(smem_dst);
    asm volatile("cp.async.cg.shared.global [%0], [%1], 16;" :: "r"(d), "l"(gmem_src));
}
__device__ __forceinline__ void cp_commit() { asm volatile("cp.async.commit_group;"); }
__device__ __forceinline__ void cp_wait0()  { asm volatile("cp.async.wait_group 0;"); }

// =====================================================================
// Kernel 0: detect mask dtype from its byte pattern (1 warp, 256 bytes)
// =====================================================================
__global__ void detect_mask_kernel(const unsigned char* __restrict__ m) {
    const int t = threadIdx.x;
    ull v = ((const ull*)m)[t];
    int ge2 = 0, off = 0;
    #pragma unroll
    for (int i = 0; i < 8; ++i) {
        unsigned char b = (unsigned char)((v >> (8 * i)) & 0xFF);
        const int j = t * 8 + i;
        if (b >= 2) ge2 = 1;
        if ((j & 3) && b) off = 1;
    }
    ge2 = __any_sync(0xFFFFFFFFu, ge2);
    off = __any_sync(0xFFFFFFFFu, off);
    if (t == 0) g_mask_dtype = ge2 ? 2 : (off ? 0 : 1);
}

// =====================================================================
// Kernel 1: e = exp(scale*QK^T masked - m_tile); stats (m,s) -> g_MS
// Tile 128x128, 256 threads, per-thread 8 rows x 8 cols (col-pairs)
// =====================================================================
__global__ __launch_bounds__(256, 2)
void qk_scores_kernel(const float* __restrict__ q, const float* __restrict__ k,
                      const void* __restrict__ mask,
                      float* __restrict__ scores) {
    extern __shared__ float sm[];
    float* Qs = sm;              // [64][128] d-major
    float* Ks = sm + 64 * 128;   // [64][128] d-major

    const int t  = threadIdx.x;
    const int bh = blockIdx.z;
    const int i0 = blockIdx.y * 128;
    const int j0 = blockIdx.x * 128;

    const float* Qg = q + ((size_t)bh * SQ + i0) * DH;
    const float* Kg = k + ((size_t)bh * SQ + j0) * DH;

    // ---- transpose-fill via 4x4 register blocks ----
    {
        const int d4 = (t & 15) * 4;
        const int rb = (t >> 4) * 4;
        #pragma unroll
        for (int p = 0; p < 2; ++p) {
            const int r0 = rb + 64 * p;
            float rq[4][4], rk[4][4];
            #pragma unroll
            for (int i = 0; i < 4; ++i) {
                float4 a = *(const float4*)(Qg + (size_t)(r0 + i) * DH + d4);
                rq[i][0] = a.x; rq[i][1] = a.y; rq[i][2] = a.z; rq[i][3] = a.w;
                float4 b = *(const float4*)(Kg + (size_t)(r0 + i) * DH + d4);
                rk[i][0] = b.x; rk[i][1] = b.y; rk[i][2] = b.z; rk[i][3] = b.w;
            }
            #pragma unroll
            for (int u = 0; u < 4; ++u) {
                *(float4*)&Qs[(d4 + u) * 128 + r0] =
                    make_float4(rq[0][u], rq[1][u], rq[2][u], rq[3][u]);
                *(float4*)&Ks[(d4 + u) * 128 + r0] =
                    make_float4(rk[0][u], rk[1][u], rk[2][u], rk[3][u]);
            }
        }
    }
    __syncthreads();

    const int ty = t >> 4;   // rows ty*8 .. +7
    const int tx = t & 15;   // cols 8*tx .. +7

    ull acc[8][4];
    #pragma unroll
    for (int i = 0; i < 8; ++i)
        #pragma unroll
        for (int j = 0; j < 4; ++j) acc[i][j] = 0ULL;

    #pragma unroll 4
    for (int d = 0; d < 64; ++d) {
        const float* qa = &Qs[d * 128 + ty * 8];
        float4 a0 = *(const float4*)qa;
        float4 a1 = *(const float4*)(qa + 4);
        ull pa[8];
        pa[0] = pk2(a0.x); pa[1] = pk2(a0.y); pa[2] = pk2(a0.z); pa[3] = pk2(a0.w);
        pa[4] = pk2(a1.x); pa[5] = pk2(a1.y); pa[6] = pk2(a1.z); pa[7] = pk2(a1.w);
        const ulonglong2* kb2 = (const ulonglong2*)&Ks[d * 128];
        ulonglong2 B0 = kb2[2 * tx], B1 = kb2[2 * tx + 1];
        #pragma unroll
        for (int ii = 0; ii < 8; ++ii) {
            fma2(acc[ii][0], pa[ii], B0.x);
            fma2(acc[ii][1], pa[ii], B0.y);
            fma2(acc[ii][2], pa[ii], B1.x);
            fma2(acc[ii][3], pa[ii], B1.y);
        }
    }

    // ---- epilogue: scale + mask + tile-local softmax numerator ----
    const int mf = g_mask_dtype;

    #pragma unroll
    for (int ii = 0; ii < 8; ++ii) {
        const int row = i0 + ty * 8 + ii;
        const size_t rbase = ((size_t)bh * SQ + row) * SQ + j0 + 8 * tx;
        float x[8];
        #pragma unroll
        for (int jj = 0; jj < 4; ++jj) {
            float2 s = unpk(acc[ii][jj]);
            x[2 * jj]     = SCL * s.x;
            x[2 * jj + 1] = SCL * s.y;
        }
        if (mf == 0) {
            ull mv = *(const ull*)((const unsigned char*)mask + rbase);
            #pragma unroll
            for (int j = 0; j < 8; ++j)
                if ((mv >> (8 * j)) & 0xFFull) x[j] = MASKF;
        } else if (mf == 1) {
            const int4* mp = (const int4*)((const int*)mask + rbase);
            int4 m0 = mp[0], m1 = mp[1];
            if (m0.x) x[0] = MASKF; if (m0.y) x[1] = MASKF;
            if (m0.z) x[2] = MASKF; if (m0.w) x[3] = MASKF;
            if (m1.x) x[4] = MASKF; if (m1.y) x[5] = MASKF;
            if (m1.z) x[6] = MASKF; if (m1.w) x[7] = MASKF;
        } else {
            const float4* mp = (const float4*)((const float*)mask + rbase);
            float4 m0 = mp[0], m1 = mp[1];
            if (m0.x != 0.0f) x[0] = MASKF; if (m0.y != 0.0f) x[1] = MASKF;
            if (m0.z != 0.0f) x[2] = MASKF; if (m0.w != 0.0f) x[3] = MASKF;
            if (m1.x != 0.0f) x[4] = MASKF; if (m1.y != 0.0f) x[5] = MASKF;
            if (m1.z != 0.0f) x[6] = MASKF; if (m1.w != 0.0f) x[7] = MASKF;
        }
        // tile-row max over 128 cols (8 local + 16 lanes)
        float m = x[0];
        #pragma unroll
        for (int j = 1; j < 8; ++j) m = fmaxf(m, x[j]);
        #pragma unroll
        for (int o = 1; o < 16; o <<= 1)
            m = fmaxf(m, __shfl_xor_sync(0xFFFFFFFFu, m, o));
        // numerators + tile sum
        float e[8], s = 0.0f;
        #pragma unroll
        for (int j = 0; j < 8; ++j) { e[j] = __expf(x[j] - m); s += e[j]; }
        #pragma unroll
        for (int o = 1; o < 16; o <<= 1)
            s += __shfl_xor_sync(0xFFFFFFFFu, s, o);

        float* orow = scores + rbase;
        *(float4*)orow       = make_float4(e[0], e[1], e[2], e[3]);
        *(float4*)(orow + 4) = make_float4(e[4], e[5], e[6], e[7]);
        if (tx == 0)
            g_MS[((size_t)bh * SQ + row) * NTILE + blockIdx.x] = make_float2(m, s);
    }
}

// =====================================================================
// Kernel 2: combine per-tile stats -> per-(row, tile) factor f
// =====================================================================
__global__ __launch_bounds__(128)
void combine_kernel() {
    const size_t row = (size_t)blockIdx.x * 128 + threadIdx.x;
    const float4* mp = (const float4*)(g_MS + row * NTILE);
    float4 r[8];
    #pragma unroll
    for (int i = 0; i < 8; ++i) r[i] = mp[i];
    float M = r[0].x;
    #pragma unroll
    for (int i = 0; i < 8; ++i) { M = fmaxf(M, r[i].x); M = fmaxf(M, r[i].z); }
    float e[16], S = 0.0f;
    #pragma unroll
    for (int i = 0; i < 8; ++i) {
        e[2 * i]     = __expf(r[i].x - M); S += r[i].y * e[2 * i];
        e[2 * i + 1] = __expf(r[i].z - M); S += r[i].w * e[2 * i + 1];
    }
    const float inv = 1.0f / S;
    float4* f = (float4*)(g_F + row * NTILE);
    #pragma unroll
    for (int i = 0; i < 4; ++i)
        f[i] = make_float4(e[4 * i] * inv, e[4 * i + 1] * inv,
                           e[4 * i + 2] * inv, e[4 * i + 3] * inv);
}

// =====================================================================
// Kernel 3: context = attn @ V; also normalizes + writes final attn.
// Tile 128 rows x 64 cols, 128 threads, per-thread 8x8, BK=32,
// double-buffered smem, cp.async for V, reg-prefetch + transform for A.
// =====================================================================
#define AV_BK 32
#define AV_LDA 132   // padded row stride of As (floats)

__global__ __launch_bounds__(128, 4)
void av_kernel(float* __restrict__ attn, const float* __restrict__ v,
               float* __restrict__ ctx) {
    extern __shared__ float sm[];
    float* Asb[2] = { sm, sm + AV_BK * AV_LDA };
    float* Vsb[2] = { sm + 2 * AV_BK * AV_LDA, sm + 2 * AV_BK * AV_LDA + AV_BK * 64 };

    const int t  = threadIdx.x;
    const int bh = blockIdx.y;
    const int i0 = blockIdx.x * 128;

    float* Ag = attn + ((size_t)bh * SQ + i0) * SQ;   // raw e-values (in/out)
    const float* Vg = v + (size_t)bh * SQ * DH;

    // load-phase mapping: kk group (t&7)*4, row group (t>>3)*4 (+64p)
    const int kg = (t & 7) * 4;
    const int rg = (t >> 3) * 4;
    // compute mapping: ty rows, tx cols
    const int ty = t >> 3;   // 16 groups of 8 rows
    const int tx = t & 7;    // 8 groups of 8 cols

    float4 ra[2][4];
    float  fvv[2][4];

    ull acc[8][4];
    #pragma unroll
    for (int i = 0; i < 8; ++i)
        #pragma unroll
        for (int j = 0; j < 4; ++j) acc[i][j] = 0ULL;

    // ---- helpers as macros via lambdas ----
    auto ldF = [&](int ktile) {
        #pragma unroll
        for (int p = 0; p < 2; ++p)
            #pragma unroll
            for (int i = 0; i < 4; ++i)
                fvv[p][i] = g_F[((size_t)bh * SQ + i0 + rg + 64 * p + i) * NTILE + ktile];
    };
    auto ldA = [&](int n) {
        #pragma unroll
        for (int p = 0; p < 2; ++p)
            #pragma unroll
            for (int i = 0; i < 4; ++i)
                ra[p][i] = *(const float4*)(Ag + (size_t)(rg + 64 * p + i) * SQ + n * AV_BK + kg);
    };
    auto ldV = [&](int n, float* VsN) {
        #pragma unroll
        for (int it = 0; it < 4; ++it) {
            const int id = it * 128 + t;
            const int kk = id >> 4;
            const int c4 = (id & 15) * 4;
            cpasync16(VsN + kk * 64 + c4, Vg + (size_t)(n * AV_BK + kk) * DH + c4);
        }
        cp_commit();
    };
    auto stA = [&](int n, float* AsN) {
        #pragma unroll
        for (int p = 0; p < 2; ++p) {
            float4 p0 = ra[p][0], p1 = ra[p][1], p2 = ra[p][2], p3 = ra[p][3];
            const float f0 = fvv[p][0], f1 = fvv[p][1], f2 = fvv[p][2], f3 = fvv[p][3];
            p0.x *= f0; p0.y *= f0; p0.z *= f0; p0.w *= f0;
            p1.x *= f1; p1.y *= f1; p1.z *= f1; p1.w *= f1;
            p2.x *= f2; p2.y *= f2; p2.z *= f2; p2.w *= f2;
            p3.x *= f3; p3.y *= f3; p3.z *= f3; p3.w *= f3;
            const int r0 = rg + 64 * p;
            // final normalized attn write-back
            *(float4*)(Ag + (size_t)(r0 + 0) * SQ + n * AV_BK + kg) = p0;
            *(float4*)(Ag + (size_t)(r0 + 1) * SQ + n * AV_BK + kg) = p1;
            *(float4*)(Ag + (size_t)(r0 + 2) * SQ + n * AV_BK + kg) = p2;
            *(float4*)(Ag + (size_t)(r0 + 3) * SQ + n * AV_BK + kg) = p3;
            // transposed store into smem (kk-major)
            float* b = AsN + r0;
            *(float4*)(b + (kg + 0) * AV_LDA) = make_float4(p0.x, p1.x, p2.x, p3.x);
            *(float4*)(b + (kg + 1) * AV_LDA) = make_float4(p0.y, p1.y, p2.y, p3.y);
            *(float4*)(b + (kg + 2) * AV_LDA) = make_float4(p0.z, p1.z, p2.z, p3.z);
            *(float4*)(b + (kg + 3) * AV_LDA) = make_float4(p0.w, p1.w, p2.w, p3.w);
        }
    };

    // ---- prologue: chunk 0 ----
    ldF(0);
    ldA(0);
    ldV(0, Vsb[0]);
    stA(0, Asb[0]);
    cp_wait0();
    __syncthreads();

    // ---- main pipelined loop over 64 chunks of BK=32 ----
    for (int c = 0; c < SQ / AV_BK; ++c) {
        const int cur = c & 1;
        if (c < SQ / AV_BK - 1) {
            const int n = c + 1;
            if ((n & 3) == 0) ldF(n >> 2);
            ldA(n);
            ldV(n, Vsb[1 - cur]);
        }
        // compute over chunk c
        {
            const float* Asc = Asb[cur];
            const float* Vsc = Vsb[cur];
            #pragma unroll 8
            for (int kk = 0; kk < AV_BK; ++kk) {
                const float* aa = Asc + kk * AV_LDA + ty * 8;
                float4 a0 = *(const float4*)aa;
                float4 a1 = *(const float4*)(aa + 4);
                ull pa[8];
                pa[0] = pk2(a0.x); pa[1] = pk2(a0.y); pa[2] = pk2(a0.z); pa[3] = pk2(a0.w);
                pa[4] = pk2(a1.x); pa[5] = pk2(a1.y); pa[6] = pk2(a1.z); pa[7] = pk2(a1.w);
                const ulonglong2* vb2 = (const ulonglong2*)(Vsc + kk * 64 + tx * 8);
                ulonglong2 B0 = vb2[0], B1 = vb2[1];
                #pragma unroll
                for (int r = 0; r < 8; ++r) {
                    fma2(acc[r][0], pa[r], B0.x);
                    fma2(acc[r][1], pa[r], B0.y);
                    fma2(acc[r][2], pa[r], B1.x);
                    fma2(acc[r][3], pa[r], B1.y);
                }
            }
        }
        if (c < SQ / AV_BK - 1) {
            stA(c + 1, Asb[1 - cur]);
            cp_wait0();
        }
        __syncthreads();
    }

    // ---- epilogue: write context ----
    #pragma unroll
    for (int r = 0; r < 8; ++r) {
        float2 c0 = unpk(acc[r][0]), c1 = unpk(acc[r][1]);
        float2 c2 = unpk(acc[r][2]), c3 = unpk(acc[r][3]);
        float* o = ctx + ((size_t)bh * SQ + i0 + ty * 8 + r) * DH + tx * 8;
        *(float4*)o       = make_float4(c0.x, c0.y, c1.x, c1.y);
        *(float4*)(o + 4) = make_float4(c2.x, c2.y, c3.x, c3.y);
    }
}

// =====================================================================
extern "C" void kernel_launch(void* const* d_in, const int* in_sizes, int n_in,
                              void* d_out, int out_size) {
    const float* q = (const float*)d_in[0];
    const float* k = (const float*)d_in[1];
    const float* v = (const float*)d_in[2];
    const void*  mask = d_in[3];

    float* ctx  = (float*)d_out;                              // [24, 2048, 64]
    float* attn = (float*)d_out + (size_t)NBH * SQ * DH;      // [24, 2048, 2048]

    cudaFuncSetAttribute(qk_scores_kernel,
                         cudaFuncAttributeMaxDynamicSharedMemorySize, 65536);
    const int av_smem = (2 * AV_BK * AV_LDA + 2 * AV_BK * 64) * sizeof(float);
    cudaFuncSetAttribute(av_kernel,
                         cudaFuncAttributeMaxDynamicSharedMemorySize, av_smem);

    detect_mask_kernel<<<1, 32>>>((const unsigned char*)mask);

    dim3 g1(SQ / 128, SQ / 128, NBH);
    qk_scores_kernel<<<g1, 256, 65536>>>(q, k, mask, attn);

    combine_kernel<<<NBH * SQ / 128, 128>>>();

    dim3 g3(SQ / 128, NBH);
    av_kernel<<<g3, 128, av_smem>>>(attn, v, ctx);
}

// round 6
// speedup vs baseline: 1.2619x; 1.2619x over previous
#include <cuda_runtime.h>
#include <cuda_bf16.h>
#include <cstdint>

#define SQ 2048
#define DH 64
#define NBH 24
#define NTILE 16
#define MASKF (-1.0e9f)
#define SCL 0.5f

typedef unsigned long long ull;

// mask dtype flag: 0 = 1-byte bool/uint8, 1 = int32, 2 = float32
__device__ int g_mask_dtype;
// per-(row, 128-col tile) partial softmax stats (m_i, s_i)
__device__ float2 g_MS[(size_t)NBH * SQ * NTILE];
// per-(row, tile) rescale factor f = exp(m_i - M) / S
__device__ float g_F[(size_t)NBH * SQ * NTILE];

// ---- packed f32x2 helpers ----
__device__ __forceinline__ ull pk2(float x) {
    ull r; asm("mov.b64 %0, {%1, %1};" : "=l"(r) : "f"(x)); return r;
}
__device__ __forceinline__ void fma2(ull& d, ull a, ull b) {
    asm("fma.rn.f32x2 %0, %1, %2, %0;" : "+l"(d) : "l"(a), "l"(b));
}
__device__ __forceinline__ float2 unpk(ull v) {
    float2 r; asm("mov.b64 {%0, %1}, %2;" : "=f"(r.x), "=f"(r.y) : "l"(v)); return r;
}
// ---- cp.async helpers ----
__device__ __forceinline__ void cpasync16(const void* smem_dst, const void* gmem_src) {
    uint32_t d = (uint32_t)__cvta_generic_to_shared(smem_dst);
    asm volatile("cp.async.cg.shared.global [%0], [%1], 16;" :: "r"(d), "l"(gmem_src));
}
__device__ __forceinline__ void cp_commit() { asm volatile("cp.async.commit_group;"); }
__device__ __forceinline__ void cp_wait0()  { asm volatile("cp.async.wait_group 0;"); }

// ---- bf16 mma.sync ----
#define MMA_BF16(d, a, b0, b1)                                                  \
    asm volatile("mma.sync.aligned.m16n8k16.row.col.f32.bf16.bf16.f32 "         \
                 "{%0,%1,%2,%3}, {%4,%5,%6,%7}, {%8,%9}, {%0,%1,%2,%3};"        \
                 : "+f"((d)[0]), "+f"((d)[1]), "+f"((d)[2]), "+f"((d)[3])       \
                 : "r"((a)[0]), "r"((a)[1]), "r"((a)[2]), "r"((a)[3]),          \
                   "r"(b0), "r"(b1))

__device__ __forceinline__ unsigned pkbf(float a, float b) {
    __nv_bfloat162 v;
    v.x = __float2bfloat16(a);
    v.y = __float2bfloat16(b);
    return *(unsigned*)&v;
}

// =====================================================================
// Kernel 0: detect mask dtype from its byte pattern (1 warp, 256 bytes)
// =====================================================================
__global__ void detect_mask_kernel(const unsigned char* __restrict__ m) {
    const int t = threadIdx.x;
    ull v = ((const ull*)m)[t];
    int ge2 = 0, off = 0;
    #pragma unroll
    for (int i = 0; i < 8; ++i) {
        unsigned char b = (unsigned char)((v >> (8 * i)) & 0xFF);
        const int j = t * 8 + i;
        if (b >= 2) ge2 = 1;
        if ((j & 3) && b) off = 1;
    }
    ge2 = __any_sync(0xFFFFFFFFu, ge2);
    off = __any_sync(0xFFFFFFFFu, off);
    if (t == 0) g_mask_dtype = ge2 ? 2 : (off ? 0 : 1);
}

// =====================================================================
// Kernel 1: tensor-core QK^T via split-bf16 (3 products), fused
// scale+mask+tile-softmax. Tile 128x128, 8 warps (4m x 2n).
// SMEM: Qh,Ql,Kh,Kl as bf16 [128][72] (pitch 72 -> conflict-free LDS.32
// fragments: bank = 4*g + tig, a 0..31 permutation).
// =====================================================================
#define QP 72          // bf16 row pitch
#define QPW 36         // pitch in 32-bit words

__global__ __launch_bounds__(256, 2)
void qk_scores_kernel(const float* __restrict__ q, const float* __restrict__ k,
                      const void* __restrict__ mask,
                      float* __restrict__ scores) {
    extern __shared__ char smem[];
    __nv_bfloat16* Qh = (__nv_bfloat16*)smem;            // 128*72
    __nv_bfloat16* Ql = Qh + 128 * QP;
    __nv_bfloat16* Kh = Ql + 128 * QP;
    __nv_bfloat16* Kl = Kh + 128 * QP;
    float* Mred = (float*)(smem + 4 * 128 * QP * 2);     // [128][2]
    float* Sred = Mred + 256;                            // [128][2]

    const int t   = threadIdx.x;
    const int bh  = blockIdx.z;
    const int i0  = blockIdx.y * 128;
    const int j0  = blockIdx.x * 128;
    const int wid = t >> 5;
    const int lane = t & 31;
    const int wm  = wid >> 1;        // 0..3 : rows wm*32..+31
    const int wn  = wid & 1;         // 0..1 : cols wn*64..+63
    const int g   = lane >> 2;       // 0..7
    const int tig = lane & 3;        // 0..3

    const float* Qg = q + ((size_t)bh * SQ + i0) * DH;
    const float* Kg = k + ((size_t)bh * SQ + j0) * DH;

    // ---- load + split-convert Q and K (fp32 -> bf16 hi/lo) ----
    #pragma unroll
    for (int i = 0; i < 8; ++i) {
        const int id  = t + 256 * i;
        const int row = id >> 4;
        const int c   = (id & 15) * 4;
        float4 x = *(const float4*)(Qg + row * DH + c);
        float h0 = __bfloat162float(__float2bfloat16(x.x));
        float h1 = __bfloat162float(__float2bfloat16(x.y));
        float h2 = __bfloat162float(__float2bfloat16(x.z));
        float h3 = __bfloat162float(__float2bfloat16(x.w));
        *(uint2*)&Qh[row * QP + c] = make_uint2(pkbf(h0, h1), pkbf(h2, h3));
        *(uint2*)&Ql[row * QP + c] =
            make_uint2(pkbf(x.x - h0, x.y - h1), pkbf(x.z - h2, x.w - h3));
        float4 y = *(const float4*)(Kg + row * DH + c);
        float k0 = __bfloat162float(__float2bfloat16(y.x));
        float k1 = __bfloat162float(__float2bfloat16(y.y));
        float k2 = __bfloat162float(__float2bfloat16(y.z));
        float k3 = __bfloat162float(__float2bfloat16(y.w));
        *(uint2*)&Kh[row * QP + c] = make_uint2(pkbf(k0, k1), pkbf(k2, k3));
        *(uint2*)&Kl[row * QP + c] =
            make_uint2(pkbf(y.x - k0, y.y - k1), pkbf(y.z - k2, y.w - k3));
    }
    __syncthreads();

    const unsigned* Qhu = (const unsigned*)Qh;
    const unsigned* Qlu = (const unsigned*)Ql;
    const unsigned* Khu = (const unsigned*)Kh;
    const unsigned* Klu = (const unsigned*)Kl;

    float acc[2][8][4];
    #pragma unroll
    for (int a = 0; a < 2; ++a)
        #pragma unroll
        for (int b = 0; b < 8; ++b)
            #pragma unroll
            for (int c = 0; c < 4; ++c) acc[a][b][c] = 0.0f;

    #pragma unroll
    for (int ks = 0; ks < 4; ++ks) {
        unsigned aH[2][4], aL[2][4];
        #pragma unroll
        for (int mi = 0; mi < 2; ++mi) {
            const int w = (wm * 32 + mi * 16 + g) * QPW + 8 * ks + tig;
            aH[mi][0] = Qhu[w];       aH[mi][1] = Qhu[w + 8 * QPW];
            aH[mi][2] = Qhu[w + 4];   aH[mi][3] = Qhu[w + 8 * QPW + 4];
            aL[mi][0] = Qlu[w];       aL[mi][1] = Qlu[w + 8 * QPW];
            aL[mi][2] = Qlu[w + 4];   aL[mi][3] = Qlu[w + 8 * QPW + 4];
        }
        #pragma unroll
        for (int ni = 0; ni < 8; ++ni) {
            const int wb = (wn * 64 + ni * 8 + g) * QPW + 8 * ks + tig;
            const unsigned bh0 = Khu[wb], bh1 = Khu[wb + 4];
            const unsigned bl0 = Klu[wb], bl1 = Klu[wb + 4];
            MMA_BF16(acc[0][ni], aH[0], bh0, bh1);
            MMA_BF16(acc[1][ni], aH[1], bh0, bh1);
            MMA_BF16(acc[0][ni], aL[0], bh0, bh1);
            MMA_BF16(acc[1][ni], aL[1], bh0, bh1);
            MMA_BF16(acc[0][ni], aH[0], bl0, bl1);
            MMA_BF16(acc[1][ni], aH[1], bl0, bl1);
        }
    }
    __syncthreads();   // smem tiles dead; reuse barrier for Mred/Sred phase

    // ---- epilogue: scale + mask, per-row-tile max/sum, exp, store ----
    const int mf = g_mask_dtype;

    // pass 1: scale + mask into acc, warp-local row max
    #pragma unroll
    for (int mi = 0; mi < 2; ++mi) {
        #pragma unroll
        for (int h = 0; h < 2; ++h) {
            const int row_l = wm * 32 + mi * 16 + h * 8 + g;
            const int grow  = i0 + row_l;
            float mm = -3.0e38f;
            #pragma unroll
            for (int ni = 0; ni < 8; ++ni) {
                float& x0 = acc[mi][ni][2 * h];
                float& x1 = acc[mi][ni][2 * h + 1];
                x0 *= SCL; x1 *= SCL;
                const size_t idx =
                    ((size_t)bh * SQ + grow) * SQ + j0 + wn * 64 + ni * 8 + 2 * tig;
                if (mf == 0) {
                    uchar2 m = *(const uchar2*)((const unsigned char*)mask + idx);
                    if (m.x) x0 = MASKF; if (m.y) x1 = MASKF;
                } else if (mf == 1) {
                    int2 m = *(const int2*)((const int*)mask + idx);
                    if (m.x) x0 = MASKF; if (m.y) x1 = MASKF;
                } else {
                    float2 m = *(const float2*)((const float*)mask + idx);
                    if (m.x != 0.0f) x0 = MASKF; if (m.y != 0.0f) x1 = MASKF;
                }
                mm = fmaxf(mm, fmaxf(x0, x1));
            }
            mm = fmaxf(mm, __shfl_xor_sync(0xFFFFFFFFu, mm, 1));
            mm = fmaxf(mm, __shfl_xor_sync(0xFFFFFFFFu, mm, 2));
            Mred[row_l * 2 + wn] = mm;
        }
    }
    __syncthreads();

    // pass 2: exp with combined max, store e-values, warp-local sum
    #pragma unroll
    for (int mi = 0; mi < 2; ++mi) {
        #pragma unroll
        for (int h = 0; h < 2; ++h) {
            const int row_l = wm * 32 + mi * 16 + h * 8 + g;
            const int grow  = i0 + row_l;
            const float m = fmaxf(Mred[row_l * 2], Mred[row_l * 2 + 1]);
            float s = 0.0f;
            #pragma unroll
            for (int ni = 0; ni < 8; ++ni) {
                const float e0 = __expf(acc[mi][ni][2 * h]     - m);
                const float e1 = __expf(acc[mi][ni][2 * h + 1] - m);
                s += e0 + e1;
                const size_t idx =
                    ((size_t)bh * SQ + grow) * SQ + j0 + wn * 64 + ni * 8 + 2 * tig;
                *(float2*)(scores + idx) = make_float2(e0, e1);
            }
            s += __shfl_xor_sync(0xFFFFFFFFu, s, 1);
            s += __shfl_xor_sync(0xFFFFFFFFu, s, 2);
            Sred[row_l * 2 + wn] = s;
        }
    }
    __syncthreads();

    // pass 3: one writer per row -> g_MS
    if (wn == 0 && tig == 0) {
        #pragma unroll
        for (int mi = 0; mi < 2; ++mi)
            #pragma unroll
            for (int h = 0; h < 2; ++h) {
                const int row_l = wm * 32 + mi * 16 + h * 8 + g;
                const int grow  = i0 + row_l;
                const float m = fmaxf(Mred[row_l * 2], Mred[row_l * 2 + 1]);
                const float S = Sred[row_l * 2] + Sred[row_l * 2 + 1];
                g_MS[((size_t)bh * SQ + grow) * NTILE + blockIdx.x] =
                    make_float2(m, S);
            }
    }
}

// =====================================================================
// Kernel 2: combine per-tile stats -> per-(row, tile) factor f
// =====================================================================
__global__ __launch_bounds__(128)
void combine_kernel() {
    const size_t row = (size_t)blockIdx.x * 128 + threadIdx.x;
    const float4* mp = (const float4*)(g_MS + row * NTILE);
    float4 r[8];
    #pragma unroll
    for (int i = 0; i < 8; ++i) r[i] = mp[i];
    float M = r[0].x;
    #pragma unroll
    for (int i = 0; i < 8; ++i) { M = fmaxf(M, r[i].x); M = fmaxf(M, r[i].z); }
    float e[16], S = 0.0f;
    #pragma unroll
    for (int i = 0; i < 8; ++i) {
        e[2 * i]     = __expf(r[i].x - M); S += r[i].y * e[2 * i];
        e[2 * i + 1] = __expf(r[i].z - M); S += r[i].w * e[2 * i + 1];
    }
    const float inv = 1.0f / S;
    float4* f = (float4*)(g_F + row * NTILE);
    #pragma unroll
    for (int i = 0; i < 4; ++i)
        f[i] = make_float4(e[4 * i] * inv, e[4 * i + 1] * inv,
                           e[4 * i + 2] * inv, e[4 * i + 3] * inv);
}

// =====================================================================
// Kernel 3: context = attn @ V; also normalizes + writes final attn.
// (unchanged from R5 — known-pass)
// =====================================================================
#define AV_BK 32
#define AV_LDA 132

__global__ __launch_bounds__(128, 4)
void av_kernel(float* __restrict__ attn, const float* __restrict__ v,
               float* __restrict__ ctx) {
    extern __shared__ float sm[];
    float* Asb[2] = { sm, sm + AV_BK * AV_LDA };
    float* Vsb[2] = { sm + 2 * AV_BK * AV_LDA, sm + 2 * AV_BK * AV_LDA + AV_BK * 64 };

    const int t  = threadIdx.x;
    const int bh = blockIdx.y;
    const int i0 = blockIdx.x * 128;

    float* Ag = attn + ((size_t)bh * SQ + i0) * SQ;
    const float* Vg = v + (size_t)bh * SQ * DH;

    const int kg = (t & 7) * 4;
    const int rg = (t >> 3) * 4;
    const int ty = t >> 3;
    const int tx = t & 7;

    float4 ra[2][4];
    float  fvv[2][4];

    ull acc[8][4];
    #pragma unroll
    for (int i = 0; i < 8; ++i)
        #pragma unroll
        for (int j = 0; j < 4; ++j) acc[i][j] = 0ULL;

    auto ldF = [&](int ktile) {
        #pragma unroll
        for (int p = 0; p < 2; ++p)
            #pragma unroll
            for (int i = 0; i < 4; ++i)
                fvv[p][i] = g_F[((size_t)bh * SQ + i0 + rg + 64 * p + i) * NTILE + ktile];
    };
    auto ldA = [&](int n) {
        #pragma unroll
        for (int p = 0; p < 2; ++p)
            #pragma unroll
            for (int i = 0; i < 4; ++i)
                ra[p][i] = *(const float4*)(Ag + (size_t)(rg + 64 * p + i) * SQ + n * AV_BK + kg);
    };
    auto ldV = [&](int n, float* VsN) {
        #pragma unroll
        for (int it = 0; it < 4; ++it) {
            const int id = it * 128 + t;
            const int kk = id >> 4;
            const int c4 = (id & 15) * 4;
            cpasync16(VsN + kk * 64 + c4, Vg + (size_t)(n * AV_BK + kk) * DH + c4);
        }
        cp_commit();
    };
    auto stA = [&](int n, float* AsN) {
        #pragma unroll
        for (int p = 0; p < 2; ++p) {
            float4 p0 = ra[p][0], p1 = ra[p][1], p2 = ra[p][2], p3 = ra[p][3];
            const float f0 = fvv[p][0], f1 = fvv[p][1], f2 = fvv[p][2], f3 = fvv[p][3];
            p0.x *= f0; p0.y *= f0; p0.z *= f0; p0.w *= f0;
            p1.x *= f1; p1.y *= f1; p1.z *= f1; p1.w *= f1;
            p2.x *= f2; p2.y *= f2; p2.z *= f2; p2.w *= f2;
            p3.x *= f3; p3.y *= f3; p3.z *= f3; p3.w *= f3;
            const int r0 = rg + 64 * p;
            *(float4*)(Ag + (size_t)(r0 + 0) * SQ + n * AV_BK + kg) = p0;
            *(float4*)(Ag + (size_t)(r0 + 1) * SQ + n * AV_BK + kg) = p1;
            *(float4*)(Ag + (size_t)(r0 + 2) * SQ + n * AV_BK + kg) = p2;
            *(float4*)(Ag + (size_t)(r0 + 3) * SQ + n * AV_BK + kg) = p3;
            float* b = AsN + r0;
            *(float4*)(b + (kg + 0) * AV_LDA) = make_float4(p0.x, p1.x, p2.x, p3.x);
            *(float4*)(b + (kg + 1) * AV_LDA) = make_float4(p0.y, p1.y, p2.y, p3.y);
            *(float4*)(b + (kg + 2) * AV_LDA) = make_float4(p0.z, p1.z, p2.z, p3.z);
            *(float4*)(b + (kg + 3) * AV_LDA) = make_float4(p0.w, p1.w, p2.w, p3.w);
        }
    };

    ldF(0);
    ldA(0);
    ldV(0, Vsb[0]);
    stA(0, Asb[0]);
    cp_wait0();
    __syncthreads();

    for (int c = 0; c < SQ / AV_BK; ++c) {
        const int cur = c & 1;
        if (c < SQ / AV_BK - 1) {
            const int n = c + 1;
            if ((n & 3) == 0) ldF(n >> 2);
            ldA(n);
            ldV(n, Vsb[1 - cur]);
        }
        {
            const float* Asc = Asb[cur];
            const float* Vsc = Vsb[cur];
            #pragma unroll 8
            for (int kk = 0; kk < AV_BK; ++kk) {
                const float* aa = Asc + kk * AV_LDA + ty * 8;
                float4 a0 = *(const float4*)aa;
                float4 a1 = *(const float4*)(aa + 4);
                ull pa[8];
                pa[0] = pk2(a0.x); pa[1] = pk2(a0.y); pa[2] = pk2(a0.z); pa[3] = pk2(a0.w);
                pa[4] = pk2(a1.x); pa[5] = pk2(a1.y); pa[6] = pk2(a1.z); pa[7] = pk2(a1.w);
                const ulonglong2* vb2 = (const ulonglong2*)(Vsc + kk * 64 + tx * 8);
                ulonglong2 B0 = vb2[0], B1 = vb2[1];
                #pragma unroll
                for (int r = 0; r < 8; ++r) {
                    fma2(acc[r][0], pa[r], B0.x);
                    fma2(acc[r][1], pa[r], B0.y);
                    fma2(acc[r][2], pa[r], B1.x);
                    fma2(acc[r][3], pa[r], B1.y);
                }
            }
        }
        if (c < SQ / AV_BK - 1) {
            stA(c + 1, Asb[1 - cur]);
            cp_wait0();
        }
        __syncthreads();
    }

    #pragma unroll
    for (int r = 0; r < 8; ++r) {
        float2 c0 = unpk(acc[r][0]), c1 = unpk(acc[r][1]);
        float2 c2 = unpk(acc[r][2]), c3 = unpk(acc[r][3]);
        float* o = ctx + ((size_t)bh * SQ + i0 + ty * 8 + r) * DH + tx * 8;
        *(float4*)o       = make_float4(c0.x, c0.y, c1.x, c1.y);
        *(float4*)(o + 4) = make_float4(c2.x, c2.y, c3.x, c3.y);
    }
}

// =====================================================================
extern "C" void kernel_launch(void* const* d_in, const int* in_sizes, int n_in,
                              void* d_out, int out_size) {
    const float* q = (const float*)d_in[0];
    const float* k = (const float*)d_in[1];
    const float* v = (const float*)d_in[2];
    const void*  mask = d_in[3];

    float* ctx  = (float*)d_out;                              // [24, 2048, 64]
    float* attn = (float*)d_out + (size_t)NBH * SQ * DH;      // [24, 2048, 2048]

    const int qk_smem = 4 * 128 * QP * 2 + 512 * 4;           // 75776
    cudaFuncSetAttribute(qk_scores_kernel,
                         cudaFuncAttributeMaxDynamicSharedMemorySize, qk_smem);
    const int av_smem = (2 * AV_BK * AV_LDA + 2 * AV_BK * 64) * sizeof(float);
    cudaFuncSetAttribute(av_kernel,
                         cudaFuncAttributeMaxDynamicSharedMemorySize, av_smem);

    detect_mask_kernel<<<1, 32>>>((const unsigned char*)mask);

    dim3 g1(SQ / 128, SQ / 128, NBH);
    qk_scores_kernel<<<g1, 256, qk_smem>>>(q, k, mask, attn);

    combine_kernel<<<NBH * SQ / 128, 128>>>();

    dim3 g3(SQ / 128, NBH);
    av_kernel<<<g3, 128, av_smem>>>(attn, v, ctx);
}

// round 7
// speedup vs baseline: 1.6842x; 1.3346x over previous
#include <cuda_runtime.h>
#include <cuda_bf16.h>
#include <cstdint>

#define SQ 2048
#define DH 64
#define NBH 24
#define NTILE 16
#define MASKF (-1.0e9f)
#define SCL 0.5f

typedef unsigned long long ull;

// mask dtype flag: 0 = 1-byte bool/uint8, 1 = int32, 2 = float32
__device__ int g_mask_dtype;
// per-(row, 128-col tile) partial softmax stats (m_i, s_i)
__device__ float2 g_MS[(size_t)NBH * SQ * NTILE];
// per-(row, tile) rescale factor f = exp(m_i - M) / S
__device__ float g_F[(size_t)NBH * SQ * NTILE];
// V transposed to [bh][d][k], split bf16 hi/lo
__device__ __nv_bfloat16 g_Vth[(size_t)NBH * DH * SQ];
__device__ __nv_bfloat16 g_Vtl[(size_t)NBH * DH * SQ];

// ---- cp.async helpers ----
__device__ __forceinline__ void cpasync16(const void* smem_dst, const void* gmem_src) {
    uint32_t d = (uint32_t)__cvta_generic_to_shared(smem_dst);
    asm volatile("cp.async.cg.shared.global [%0], [%1], 16;" :: "r"(d), "l"(gmem_src));
}
__device__ __forceinline__ void cp_commit() { asm volatile("cp.async.commit_group;"); }
__device__ __forceinline__ void cp_wait0()  { asm volatile("cp.async.wait_group 0;"); }

// ---- bf16 mma.sync ----
#define MMA_BF16(d, a, b0, b1)                                                  \
    asm volatile("mma.sync.aligned.m16n8k16.row.col.f32.bf16.bf16.f32 "         \
                 "{%0,%1,%2,%3}, {%4,%5,%6,%7}, {%8,%9}, {%0,%1,%2,%3};"        \
                 : "+f"((d)[0]), "+f"((d)[1]), "+f"((d)[2]), "+f"((d)[3])       \
                 : "r"((a)[0]), "r"((a)[1]), "r"((a)[2]), "r"((a)[3]),          \
                   "r"(b0), "r"(b1))

__device__ __forceinline__ unsigned pkbf(float a, float b) {
    __nv_bfloat162 v;
    v.x = __float2bfloat16(a);
    v.y = __float2bfloat16(b);
    return *(unsigned*)&v;
}

// =====================================================================
// Kernel 0: detect mask dtype from its byte pattern (1 warp, 256 bytes)
// =====================================================================
__global__ void detect_mask_kernel(const unsigned char* __restrict__ m) {
    const int t = threadIdx.x;
    ull v = ((const ull*)m)[t];
    int ge2 = 0, off = 0;
    #pragma unroll
    for (int i = 0; i < 8; ++i) {
        unsigned char b = (unsigned char)((v >> (8 * i)) & 0xFF);
        const int j = t * 8 + i;
        if (b >= 2) ge2 = 1;
        if ((j & 3) && b) off = 1;
    }
    ge2 = __any_sync(0xFFFFFFFFu, ge2);
    off = __any_sync(0xFFFFFFFFu, off);
    if (t == 0) g_mask_dtype = ge2 ? 2 : (off ? 0 : 1);
}

// =====================================================================
// Kernel 0b: V -> transposed split-bf16 buffers Vt[d][k]
// =====================================================================
__global__ __launch_bounds__(256)
void vconv_kernel(const float* __restrict__ v) {
    __shared__ float s[64][65];
    const int bh = blockIdx.y;
    const int k0 = blockIdx.x * 64;
    const int t  = threadIdx.x;
    const float* Vg = v + ((size_t)bh * SQ + k0) * DH;
    {
        const int kk = t >> 2, dg = (t & 3) * 16;
        #pragma unroll
        for (int i = 0; i < 4; ++i) {
            float4 x = *(const float4*)(Vg + (size_t)kk * DH + dg + 4 * i);
            s[kk][dg + 4 * i + 0] = x.x; s[kk][dg + 4 * i + 1] = x.y;
            s[kk][dg + 4 * i + 2] = x.z; s[kk][dg + 4 * i + 3] = x.w;
        }
    }
    __syncthreads();
    {
        const int d = t >> 2, kg = (t & 3) * 16;
        __nv_bfloat16 hi[16], lo[16];
        #pragma unroll
        for (int i = 0; i < 16; ++i) {
            float x = s[kg + i][d];
            __nv_bfloat16 h = __float2bfloat16(x);
            hi[i] = h;
            lo[i] = __float2bfloat16(x - __bfloat162float(h));
        }
        const size_t off = ((size_t)bh * DH + d) * SQ + k0 + kg;
        *(uint4*)&g_Vth[off]     = *(uint4*)hi;
        *(uint4*)&g_Vth[off + 8] = *(uint4*)(hi + 8);
        *(uint4*)&g_Vtl[off]     = *(uint4*)lo;
        *(uint4*)&g_Vtl[off + 8] = *(uint4*)(lo + 8);
    }
}

// =====================================================================
// Kernel 1: tensor-core QK^T via split-bf16 (3 products), fused
// scale+mask+tile-softmax. Tile 128x128, 8 warps (4m x 2n). (R6, unchanged)
// =====================================================================
#define QP 72          // bf16 row pitch
#define QPW 36         // pitch in 32-bit words

__global__ __launch_bounds__(256, 2)
void qk_scores_kernel(const float* __restrict__ q, const float* __restrict__ k,
                      const void* __restrict__ mask,
                      float* __restrict__ scores) {
    extern __shared__ char smem[];
    __nv_bfloat16* Qh = (__nv_bfloat16*)smem;
    __nv_bfloat16* Ql = Qh + 128 * QP;
    __nv_bfloat16* Kh = Ql + 128 * QP;
    __nv_bfloat16* Kl = Kh + 128 * QP;
    float* Mred = (float*)(smem + 4 * 128 * QP * 2);
    float* Sred = Mred + 256;

    const int t   = threadIdx.x;
    const int bh  = blockIdx.z;
    const int i0  = blockIdx.y * 128;
    const int j0  = blockIdx.x * 128;
    const int wid = t >> 5;
    const int lane = t & 31;
    const int wm  = wid >> 1;
    const int wn  = wid & 1;
    const int g   = lane >> 2;
    const int tig = lane & 3;

    const float* Qg = q + ((size_t)bh * SQ + i0) * DH;
    const float* Kg = k + ((size_t)bh * SQ + j0) * DH;

    #pragma unroll
    for (int i = 0; i < 8; ++i) {
        const int id  = t + 256 * i;
        const int row = id >> 4;
        const int c   = (id & 15) * 4;
        float4 x = *(const float4*)(Qg + row * DH + c);
        float h0 = __bfloat162float(__float2bfloat16(x.x));
        float h1 = __bfloat162float(__float2bfloat16(x.y));
        float h2 = __bfloat162float(__float2bfloat16(x.z));
        float h3 = __bfloat162float(__float2bfloat16(x.w));
        *(uint2*)&Qh[row * QP + c] = make_uint2(pkbf(h0, h1), pkbf(h2, h3));
        *(uint2*)&Ql[row * QP + c] =
            make_uint2(pkbf(x.x - h0, x.y - h1), pkbf(x.z - h2, x.w - h3));
        float4 y = *(const float4*)(Kg + row * DH + c);
        float k0 = __bfloat162float(__float2bfloat16(y.x));
        float k1 = __bfloat162float(__float2bfloat16(y.y));
        float k2 = __bfloat162float(__float2bfloat16(y.z));
        float k3 = __bfloat162float(__float2bfloat16(y.w));
        *(uint2*)&Kh[row * QP + c] = make_uint2(pkbf(k0, k1), pkbf(k2, k3));
        *(uint2*)&Kl[row * QP + c] =
            make_uint2(pkbf(y.x - k0, y.y - k1), pkbf(y.z - k2, y.w - k3));
    }
    __syncthreads();

    const unsigned* Qhu = (const unsigned*)Qh;
    const unsigned* Qlu = (const unsigned*)Ql;
    const unsigned* Khu = (const unsigned*)Kh;
    const unsigned* Klu = (const unsigned*)Kl;

    float acc[2][8][4];
    #pragma unroll
    for (int a = 0; a < 2; ++a)
        #pragma unroll
        for (int b = 0; b < 8; ++b)
            #pragma unroll
            for (int c = 0; c < 4; ++c) acc[a][b][c] = 0.0f;

    #pragma unroll
    for (int ks = 0; ks < 4; ++ks) {
        unsigned aH[2][4], aL[2][4];
        #pragma unroll
        for (int mi = 0; mi < 2; ++mi) {
            const int w = (wm * 32 + mi * 16 + g) * QPW + 8 * ks + tig;
            aH[mi][0] = Qhu[w];       aH[mi][1] = Qhu[w + 8 * QPW];
            aH[mi][2] = Qhu[w + 4];   aH[mi][3] = Qhu[w + 8 * QPW + 4];
            aL[mi][0] = Qlu[w];       aL[mi][1] = Qlu[w + 8 * QPW];
            aL[mi][2] = Qlu[w + 4];   aL[mi][3] = Qlu[w + 8 * QPW + 4];
        }
        #pragma unroll
        for (int ni = 0; ni < 8; ++ni) {
            const int wb = (wn * 64 + ni * 8 + g) * QPW + 8 * ks + tig;
            const unsigned bh0 = Khu[wb], bh1 = Khu[wb + 4];
            const unsigned bl0 = Klu[wb], bl1 = Klu[wb + 4];
            MMA_BF16(acc[0][ni], aH[0], bh0, bh1);
            MMA_BF16(acc[1][ni], aH[1], bh0, bh1);
            MMA_BF16(acc[0][ni], aL[0], bh0, bh1);
            MMA_BF16(acc[1][ni], aL[1], bh0, bh1);
            MMA_BF16(acc[0][ni], aH[0], bl0, bl1);
            MMA_BF16(acc[1][ni], aH[1], bl0, bl1);
        }
    }
    __syncthreads();

    const int mf = g_mask_dtype;

    #pragma unroll
    for (int mi = 0; mi < 2; ++mi) {
        #pragma unroll
        for (int h = 0; h < 2; ++h) {
            const int row_l = wm * 32 + mi * 16 + h * 8 + g;
            const int grow  = i0 + row_l;
            float mm = -3.0e38f;
            #pragma unroll
            for (int ni = 0; ni < 8; ++ni) {
                float& x0 = acc[mi][ni][2 * h];
                float& x1 = acc[mi][ni][2 * h + 1];
                x0 *= SCL; x1 *= SCL;
                const size_t idx =
                    ((size_t)bh * SQ + grow) * SQ + j0 + wn * 64 + ni * 8 + 2 * tig;
                if (mf == 0) {
                    uchar2 m = *(const uchar2*)((const unsigned char*)mask + idx);
                    if (m.x) x0 = MASKF; if (m.y) x1 = MASKF;
                } else if (mf == 1) {
                    int2 m = *(const int2*)((const int*)mask + idx);
                    if (m.x) x0 = MASKF; if (m.y) x1 = MASKF;
                } else {
                    float2 m = *(const float2*)((const float*)mask + idx);
                    if (m.x != 0.0f) x0 = MASKF; if (m.y != 0.0f) x1 = MASKF;
                }
                mm = fmaxf(mm, fmaxf(x0, x1));
            }
            mm = fmaxf(mm, __shfl_xor_sync(0xFFFFFFFFu, mm, 1));
            mm = fmaxf(mm, __shfl_xor_sync(0xFFFFFFFFu, mm, 2));
            Mred[row_l * 2 + wn] = mm;
        }
    }
    __syncthreads();

    #pragma unroll
    for (int mi = 0; mi < 2; ++mi) {
        #pragma unroll
        for (int h = 0; h < 2; ++h) {
            const int row_l = wm * 32 + mi * 16 + h * 8 + g;
            const int grow  = i0 + row_l;
            const float m = fmaxf(Mred[row_l * 2], Mred[row_l * 2 + 1]);
            float s = 0.0f;
            #pragma unroll
            for (int ni = 0; ni < 8; ++ni) {
                const float e0 = __expf(acc[mi][ni][2 * h]     - m);
                const float e1 = __expf(acc[mi][ni][2 * h + 1] - m);
                s += e0 + e1;
                const size_t idx =
                    ((size_t)bh * SQ + grow) * SQ + j0 + wn * 64 + ni * 8 + 2 * tig;
                *(float2*)(scores + idx) = make_float2(e0, e1);
            }
            s += __shfl_xor_sync(0xFFFFFFFFu, s, 1);
            s += __shfl_xor_sync(0xFFFFFFFFu, s, 2);
            Sred[row_l * 2 + wn] = s;
        }
    }
    __syncthreads();

    if (wn == 0 && tig == 0) {
        #pragma unroll
        for (int mi = 0; mi < 2; ++mi)
            #pragma unroll
            for (int h = 0; h < 2; ++h) {
                const int row_l = wm * 32 + mi * 16 + h * 8 + g;
                const int grow  = i0 + row_l;
                const float m = fmaxf(Mred[row_l * 2], Mred[row_l * 2 + 1]);
                const float S = Sred[row_l * 2] + Sred[row_l * 2 + 1];
                g_MS[((size_t)bh * SQ + grow) * NTILE + blockIdx.x] =
                    make_float2(m, S);
            }
    }
}

// =====================================================================
// Kernel 2: combine per-tile stats -> per-(row, tile) factor f
// =====================================================================
__global__ __launch_bounds__(128)
void combine_kernel() {
    const size_t row = (size_t)blockIdx.x * 128 + threadIdx.x;
    const float4* mp = (const float4*)(g_MS + row * NTILE);
    float4 r[8];
    #pragma unroll
    for (int i = 0; i < 8; ++i) r[i] = mp[i];
    float M = r[0].x;
    #pragma unroll
    for (int i = 0; i < 8; ++i) { M = fmaxf(M, r[i].x); M = fmaxf(M, r[i].z); }
    float e[16], S = 0.0f;
    #pragma unroll
    for (int i = 0; i < 8; ++i) {
        e[2 * i]     = __expf(r[i].x - M); S += r[i].y * e[2 * i];
        e[2 * i + 1] = __expf(r[i].z - M); S += r[i].w * e[2 * i + 1];
    }
    const float inv = 1.0f / S;
    float4* f = (float4*)(g_F + row * NTILE);
    #pragma unroll
    for (int i = 0; i < 4; ++i)
        f[i] = make_float4(e[4 * i] * inv, e[4 * i + 1] * inv,
                           e[4 * i + 2] * inv, e[4 * i + 3] * inv);
}

// =====================================================================
// Kernel 3: context = attn @ V via split-bf16 tensor cores.
// Also normalizes e-values and writes final attn (fused).
// Tile 128 rows x 64 cols, 256 threads (8 warps: 4m x 2n), BK=64,
// double-buffered As (bf16 hi/lo from reg-prefetched e-values) and
// Vs (cp.async from preconverted Vt buffers).
// =====================================================================
#define AVP 72
#define AVPW 36
#define AV_BK 64

__global__ __launch_bounds__(256, 2)
void av_kernel(float* __restrict__ attn, float* __restrict__ ctx) {
    extern __shared__ char smem[];
    __nv_bfloat16* base = (__nv_bfloat16*)smem;
    __nv_bfloat16* AsH[2] = { base,                base + 2 * 128 * AVP };
    __nv_bfloat16* AsL[2] = { base + 128 * AVP,    base + 3 * 128 * AVP };
    __nv_bfloat16* vb = base + 4 * 128 * AVP;
    __nv_bfloat16* VsH[2] = { vb,                  vb + 2 * 64 * AVP };
    __nv_bfloat16* VsL[2] = { vb + 64 * AVP,       vb + 3 * 64 * AVP };

    const int t   = threadIdx.x;
    const int bh  = blockIdx.y;
    const int i0  = blockIdx.x * 128;
    const int wid = t >> 5;
    const int lane = t & 31;
    const int wm  = wid >> 1;        // rows wm*32..+31
    const int wn  = wid & 1;         // cols wn*32..+31
    const int g   = lane >> 2;
    const int tig = lane & 3;

    float* Ag = attn + ((size_t)bh * SQ + i0) * SQ;
    const __nv_bfloat16* Vth = g_Vth + (size_t)bh * DH * SQ;
    const __nv_bfloat16* Vtl = g_Vtl + (size_t)bh * DH * SQ;

    // load/proc mapping: 4 rows x 8 k per thread
    const int rg = (t >> 3) * 4;     // rows rg..rg+3
    const int kg = (t & 7) * 8;      // k cols kg..kg+7

    float4 ra[8];                    // prefetched e-values: row i -> ra[2i],ra[2i+1]
    float  fv[4];

    float acc[2][4][4];
    #pragma unroll
    for (int a = 0; a < 2; ++a)
        #pragma unroll
        for (int b = 0; b < 4; ++b)
            #pragma unroll
            for (int c = 0; c < 4; ++c) acc[a][b][c] = 0.0f;

    auto ldF = [&](int kt) {
        #pragma unroll
        for (int i = 0; i < 4; ++i)
            fv[i] = g_F[((size_t)bh * SQ + i0 + rg + i) * NTILE + kt];
    };
    auto ldA = [&](int n) {
        #pragma unroll
        for (int i = 0; i < 4; ++i) {
            const float* p = Ag + (size_t)(rg + i) * SQ + n * AV_BK + kg;
            ra[2 * i]     = *(const float4*)p;
            ra[2 * i + 1] = *(const float4*)(p + 4);
        }
    };
    auto ldV = [&](int n, int buf) {
        #pragma unroll
        for (int it = 0; it < 2; ++it) {
            const int id  = it * 256 + t;     // 0..511
            const int d   = id >> 3;
            const int seg = (id & 7) * 8;
            cpasync16(VsH[buf] + d * AVP + seg, Vth + (size_t)d * SQ + n * AV_BK + seg);
            cpasync16(VsL[buf] + d * AVP + seg, Vtl + (size_t)d * SQ + n * AV_BK + seg);
        }
        cp_commit();
    };
    auto procA = [&](int n, int buf) {
        #pragma unroll
        for (int i = 0; i < 4; ++i) {
            const int row = rg + i;
            const float f = fv[i];
            float4 a = ra[2 * i], b = ra[2 * i + 1];
            a.x *= f; a.y *= f; a.z *= f; a.w *= f;
            b.x *= f; b.y *= f; b.z *= f; b.w *= f;
            float* p = Ag + (size_t)row * SQ + n * AV_BK + kg;
            *(float4*)p       = a;
            *(float4*)(p + 4) = b;
            float h0 = __bfloat162float(__float2bfloat16(a.x));
            float h1 = __bfloat162float(__float2bfloat16(a.y));
            float h2 = __bfloat162float(__float2bfloat16(a.z));
            float h3 = __bfloat162float(__float2bfloat16(a.w));
            float h4 = __bfloat162float(__float2bfloat16(b.x));
            float h5 = __bfloat162float(__float2bfloat16(b.y));
            float h6 = __bfloat162float(__float2bfloat16(b.z));
            float h7 = __bfloat162float(__float2bfloat16(b.w));
            *(uint4*)&AsH[buf][row * AVP + kg] =
                make_uint4(pkbf(h0, h1), pkbf(h2, h3), pkbf(h4, h5), pkbf(h6, h7));
            *(uint4*)&AsL[buf][row * AVP + kg] =
                make_uint4(pkbf(a.x - h0, a.y - h1), pkbf(a.z - h2, a.w - h3),
                           pkbf(b.x - h4, b.y - h5), pkbf(b.z - h6, b.w - h7));
        }
    };

    // ---- prologue ----
    ldF(0);
    ldA(0);
    ldV(0, 0);
    procA(0, 0);
    cp_wait0();
    __syncthreads();

    // ---- main loop: 32 chunks of BK=64 ----
    for (int c = 0; c < SQ / AV_BK; ++c) {
        const int cur = c & 1;
        if (c < SQ / AV_BK - 1) {
            const int n = c + 1;
            if ((n & 1) == 0) ldF(n >> 1);
            ldA(n);
            ldV(n, 1 - cur);
        }
        {
            const unsigned* AH = (const unsigned*)AsH[cur];
            const unsigned* AL = (const unsigned*)AsL[cur];
            const unsigned* VH = (const unsigned*)VsH[cur];
            const unsigned* VL = (const unsigned*)VsL[cur];
            #pragma unroll
            for (int ks = 0; ks < 4; ++ks) {
                unsigned aH[2][4], aL[2][4];
                #pragma unroll
                for (int mi = 0; mi < 2; ++mi) {
                    const int w = (wm * 32 + mi * 16 + g) * AVPW + 8 * ks + tig;
                    aH[mi][0] = AH[w];       aH[mi][1] = AH[w + 8 * AVPW];
                    aH[mi][2] = AH[w + 4];   aH[mi][3] = AH[w + 8 * AVPW + 4];
                    aL[mi][0] = AL[w];       aL[mi][1] = AL[w + 8 * AVPW];
                    aL[mi][2] = AL[w + 4];   aL[mi][3] = AL[w + 8 * AVPW + 4];
                }
                #pragma unroll
                for (int ni = 0; ni < 4; ++ni) {
                    const int wb = (wn * 32 + ni * 8 + g) * AVPW + 8 * ks + tig;
                    const unsigned bh0 = VH[wb], bh1 = VH[wb + 4];
                    const unsigned bl0 = VL[wb], bl1 = VL[wb + 4];
                    MMA_BF16(acc[0][ni], aH[0], bh0, bh1);
                    MMA_BF16(acc[1][ni], aH[1], bh0, bh1);
                    MMA_BF16(acc[0][ni], aL[0], bh0, bh1);
                    MMA_BF16(acc[1][ni], aL[1], bh0, bh1);
                    MMA_BF16(acc[0][ni], aH[0], bl0, bl1);
                    MMA_BF16(acc[1][ni], aH[1], bl0, bl1);
                }
            }
        }
        if (c < SQ / AV_BK - 1) {
            procA(c + 1, 1 - cur);
            cp_wait0();
        }
        __syncthreads();
    }

    // ---- epilogue: write context ----
    #pragma unroll
    for (int mi = 0; mi < 2; ++mi)
        #pragma unroll
        for (int ni = 0; ni < 4; ++ni)
            #pragma unroll
            for (int h = 0; h < 2; ++h) {
                const int row = i0 + wm * 32 + mi * 16 + h * 8 + g;
                const int col = wn * 32 + ni * 8 + 2 * tig;
                *(float2*)(ctx + ((size_t)bh * SQ + row) * DH + col) =
                    make_float2(acc[mi][ni][2 * h], acc[mi][ni][2 * h + 1]);
            }
}

// =====================================================================
extern "C" void kernel_launch(void* const* d_in, const int* in_sizes, int n_in,
                              void* d_out, int out_size) {
    const float* q = (const float*)d_in[0];
    const float* k = (const float*)d_in[1];
    const float* v = (const float*)d_in[2];
    const void*  mask = d_in[3];

    float* ctx  = (float*)d_out;                              // [24, 2048, 64]
    float* attn = (float*)d_out + (size_t)NBH * SQ * DH;      // [24, 2048, 2048]

    const int qk_smem = 4 * 128 * QP * 2 + 512 * 4;           // 75776
    cudaFuncSetAttribute(qk_scores_kernel,
                         cudaFuncAttributeMaxDynamicSharedMemorySize, qk_smem);
    const int av_smem = (4 * 128 * AVP + 4 * 64 * AVP) * 2;   // 110592
    cudaFuncSetAttribute(av_kernel,
                         cudaFuncAttributeMaxDynamicSharedMemorySize, av_smem);

    detect_mask_kernel<<<1, 32>>>((const unsigned char*)mask);

    dim3 gv(SQ / 64, NBH);
    vconv_kernel<<<gv, 256>>>(v);

    dim3 g1(SQ / 128, SQ / 128, NBH);
    qk_scores_kernel<<<g1, 256, qk_smem>>>(q, k, mask, attn);

    combine_kernel<<<NBH * SQ / 128, 128>>>();

    dim3 g3(SQ / 128, NBH);
    av_kernel<<<g3, 256, av_smem>>>(attn, ctx);
}

// round 9
// speedup vs baseline: 2.0033x; 1.1895x over previous
#include <cuda_runtime.h>
#include <cuda_bf16.h>
#include <cuda_fp16.h>
#include <cstdint>

#define SQ 2048
#define DH 64
#define NBH 24
#define NTILE 16
#define MASKF (-1.0e9f)
#define SCL 0.5f

typedef unsigned long long ull;

// mask dtype flag: 0 = 1-byte bool/uint8, 1 = int32, 2 = float32
__device__ int g_mask_dtype;
// per-(row, 128-col tile) partial softmax stats (m_i, s_i)
__device__ float2 g_MS[(size_t)NBH * SQ * NTILE];
// per-(row, tile) rescale factor f = exp(m_i - M) / S
__device__ float g_F[(size_t)NBH * SQ * NTILE];
// V transposed to [bh][d][k], split fp16 hi/lo
__device__ __half g_Vth[(size_t)NBH * DH * SQ];
__device__ __half g_Vtl[(size_t)NBH * DH * SQ];
// unnormalized softmax numerators e = exp(x - m_tile), fp16 (dedicated scratch)
__device__ __half g_E[(size_t)NBH * SQ * SQ];

// ---- cp.async helpers ----
__device__ __forceinline__ void cpasync16(const void* smem_dst, const void* gmem_src) {
    uint32_t d = (uint32_t)__cvta_generic_to_shared(smem_dst);
    asm volatile("cp.async.cg.shared.global [%0], [%1], 16;" :: "r"(d), "l"(gmem_src));
}
__device__ __forceinline__ void cp_commit() { asm volatile("cp.async.commit_group;"); }
__device__ __forceinline__ void cp_wait0()  { asm volatile("cp.async.wait_group 0;"); }

// ---- mma.sync macros ----
#define MMA_BF16(d, a, b0, b1)                                                  \
    asm volatile("mma.sync.aligned.m16n8k16.row.col.f32.bf16.bf16.f32 "         \
                 "{%0,%1,%2,%3}, {%4,%5,%6,%7}, {%8,%9}, {%0,%1,%2,%3};"        \
                 : "+f"((d)[0]), "+f"((d)[1]), "+f"((d)[2]), "+f"((d)[3])       \
                 : "r"((a)[0]), "r"((a)[1]), "r"((a)[2]), "r"((a)[3]),          \
                   "r"(b0), "r"(b1))

#define MMA_F16(d, a, b0, b1)                                                   \
    asm volatile("mma.sync.aligned.m16n8k16.row.col.f32.f16.f16.f32 "           \
                 "{%0,%1,%2,%3}, {%4,%5,%6,%7}, {%8,%9}, {%0,%1,%2,%3};"        \
                 : "+f"((d)[0]), "+f"((d)[1]), "+f"((d)[2]), "+f"((d)[3])       \
                 : "r"((a)[0]), "r"((a)[1]), "r"((a)[2]), "r"((a)[3]),          \
                   "r"(b0), "r"(b1))

__device__ __forceinline__ unsigned pkbf(float a, float b) {
    __nv_bfloat162 v;
    v.x = __float2bfloat16(a);
    v.y = __float2bfloat16(b);
    return *(unsigned*)&v;
}

// =====================================================================
// Kernel 0: detect mask dtype from its byte pattern (1 warp, 256 bytes)
// =====================================================================
__global__ void detect_mask_kernel(const unsigned char* __restrict__ m) {
    const int t = threadIdx.x;
    ull v = ((const ull*)m)[t];
    int ge2 = 0, off = 0;
    #pragma unroll
    for (int i = 0; i < 8; ++i) {
        unsigned char b = (unsigned char)((v >> (8 * i)) & 0xFF);
        const int j = t * 8 + i;
        if (b >= 2) ge2 = 1;
        if ((j & 3) && b) off = 1;
    }
    ge2 = __any_sync(0xFFFFFFFFu, ge2);
    off = __any_sync(0xFFFFFFFFu, off);
    if (t == 0) g_mask_dtype = ge2 ? 2 : (off ? 0 : 1);
}

// =====================================================================
// Kernel 0b: V -> transposed split-fp16 buffers Vt[d][k]
// =====================================================================
__global__ __launch_bounds__(256)
void vconv_kernel(const float* __restrict__ v) {
    __shared__ float s[64][65];
    const int bh = blockIdx.y;
    const int k0 = blockIdx.x * 64;
    const int t  = threadIdx.x;
    const float* Vg = v + ((size_t)bh * SQ + k0) * DH;
    {
        const int kk = t >> 2, dg = (t & 3) * 16;
        #pragma unroll
        for (int i = 0; i < 4; ++i) {
            float4 x = *(const float4*)(Vg + (size_t)kk * DH + dg + 4 * i);
            s[kk][dg + 4 * i + 0] = x.x; s[kk][dg + 4 * i + 1] = x.y;
            s[kk][dg + 4 * i + 2] = x.z; s[kk][dg + 4 * i + 3] = x.w;
        }
    }
    __syncthreads();
    {
        const int d = t >> 2, kg = (t & 3) * 16;
        __half hi[16], lo[16];
        #pragma unroll
        for (int i = 0; i < 16; ++i) {
            float x = s[kg + i][d];
            __half h = __float2half_rn(x);
            hi[i] = h;
            lo[i] = __float2half_rn(x - __half2float(h));
        }
        const size_t off = ((size_t)bh * DH + d) * SQ + k0 + kg;
        *(uint4*)&g_Vth[off]     = *(uint4*)hi;
        *(uint4*)&g_Vth[off + 8] = *(uint4*)(hi + 8);
        *(uint4*)&g_Vtl[off]     = *(uint4*)lo;
        *(uint4*)&g_Vtl[off + 8] = *(uint4*)(lo + 8);
    }
}

// =====================================================================
// Kernel 1: tensor-core QK^T via split-bf16 (3 products), fused
// scale+mask+tile-softmax. e-values stored fp16 -> g_E. 128x128, 8 warps.
// =====================================================================
#define QP 72          // bf16 row pitch
#define QPW 36         // pitch in 32-bit words

__global__ __launch_bounds__(256, 2)
void qk_scores_kernel(const float* __restrict__ q, const float* __restrict__ k,
                      const void* __restrict__ mask) {
    extern __shared__ char smem[];
    __nv_bfloat16* Qh = (__nv_bfloat16*)smem;
    __nv_bfloat16* Ql = Qh + 128 * QP;
    __nv_bfloat16* Kh = Ql + 128 * QP;
    __nv_bfloat16* Kl = Kh + 128 * QP;
    float* Mred = (float*)(smem + 4 * 128 * QP * 2);
    float* Sred = Mred + 256;

    const int t   = threadIdx.x;
    const int bh  = blockIdx.z;
    const int i0  = blockIdx.y * 128;
    const int j0  = blockIdx.x * 128;
    const int wid = t >> 5;
    const int lane = t & 31;
    const int wm  = wid >> 1;
    const int wn  = wid & 1;
    const int g   = lane >> 2;
    const int tig = lane & 3;

    const float* Qg = q + ((size_t)bh * SQ + i0) * DH;
    const float* Kg = k + ((size_t)bh * SQ + j0) * DH;

    #pragma unroll
    for (int i = 0; i < 8; ++i) {
        const int id  = t + 256 * i;
        const int row = id >> 4;
        const int c   = (id & 15) * 4;
        float4 x = *(const float4*)(Qg + row * DH + c);
        float h0 = __bfloat162float(__float2bfloat16(x.x));
        float h1 = __bfloat162float(__float2bfloat16(x.y));
        float h2 = __bfloat162float(__float2bfloat16(x.z));
        float h3 = __bfloat162float(__float2bfloat16(x.w));
        *(uint2*)&Qh[row * QP + c] = make_uint2(pkbf(h0, h1), pkbf(h2, h3));
        *(uint2*)&Ql[row * QP + c] =
            make_uint2(pkbf(x.x - h0, x.y - h1), pkbf(x.z - h2, x.w - h3));
        float4 y = *(const float4*)(Kg + row * DH + c);
        float k0 = __bfloat162float(__float2bfloat16(y.x));
        float k1 = __bfloat162float(__float2bfloat16(y.y));
        float k2 = __bfloat162float(__float2bfloat16(y.z));
        float k3 = __bfloat162float(__float2bfloat16(y.w));
        *(uint2*)&Kh[row * QP + c] = make_uint2(pkbf(k0, k1), pkbf(k2, k3));
        *(uint2*)&Kl[row * QP + c] =
            make_uint2(pkbf(y.x - k0, y.y - k1), pkbf(y.z - k2, y.w - k3));
    }
    __syncthreads();

    const unsigned* Qhu = (const unsigned*)Qh;
    const unsigned* Qlu = (const unsigned*)Ql;
    const unsigned* Khu = (const unsigned*)Kh;
    const unsigned* Klu = (const unsigned*)Kl;

    float acc[2][8][4];
    #pragma unroll
    for (int a = 0; a < 2; ++a)
        #pragma unroll
        for (int b = 0; b < 8; ++b)
            #pragma unroll
            for (int c = 0; c < 4; ++c) acc[a][b][c] = 0.0f;

    #pragma unroll
    for (int ks = 0; ks < 4; ++ks) {
        unsigned aH[2][4], aL[2][4];
        #pragma unroll
        for (int mi = 0; mi < 2; ++mi) {
            const int w = (wm * 32 + mi * 16 + g) * QPW + 8 * ks + tig;
            aH[mi][0] = Qhu[w];       aH[mi][1] = Qhu[w + 8 * QPW];
            aH[mi][2] = Qhu[w + 4];   aH[mi][3] = Qhu[w + 8 * QPW + 4];
            aL[mi][0] = Qlu[w];       aL[mi][1] = Qlu[w + 8 * QPW];
            aL[mi][2] = Qlu[w + 4];   aL[mi][3] = Qlu[w + 8 * QPW + 4];
        }
        #pragma unroll
        for (int ni = 0; ni < 8; ++ni) {
            const int wb = (wn * 64 + ni * 8 + g) * QPW + 8 * ks + tig;
            const unsigned bh0 = Khu[wb], bh1 = Khu[wb + 4];
            const unsigned bl0 = Klu[wb], bl1 = Klu[wb + 4];
            MMA_BF16(acc[0][ni], aH[0], bh0, bh1);
            MMA_BF16(acc[1][ni], aH[1], bh0, bh1);
            MMA_BF16(acc[0][ni], aL[0], bh0, bh1);
            MMA_BF16(acc[1][ni], aL[1], bh0, bh1);
            MMA_BF16(acc[0][ni], aH[0], bl0, bl1);
            MMA_BF16(acc[1][ni], aH[1], bl0, bl1);
        }
    }
    __syncthreads();

    const int mf = g_mask_dtype;

    #pragma unroll
    for (int mi = 0; mi < 2; ++mi) {
        #pragma unroll
        for (int h = 0; h < 2; ++h) {
            const int row_l = wm * 32 + mi * 16 + h * 8 + g;
            const int grow  = i0 + row_l;
            float mm = -3.0e38f;
            #pragma unroll
            for (int ni = 0; ni < 8; ++ni) {
                float& x0 = acc[mi][ni][2 * h];
                float& x1 = acc[mi][ni][2 * h + 1];
                x0 *= SCL; x1 *= SCL;
                const size_t idx =
                    ((size_t)bh * SQ + grow) * SQ + j0 + wn * 64 + ni * 8 + 2 * tig;
                if (mf == 0) {
                    uchar2 m = *(const uchar2*)((const unsigned char*)mask + idx);
                    if (m.x) x0 = MASKF; if (m.y) x1 = MASKF;
                } else if (mf == 1) {
                    int2 m = *(const int2*)((const int*)mask + idx);
                    if (m.x) x0 = MASKF; if (m.y) x1 = MASKF;
                } else {
                    float2 m = *(const float2*)((const float*)mask + idx);
                    if (m.x != 0.0f) x0 = MASKF; if (m.y != 0.0f) x1 = MASKF;
                }
                mm = fmaxf(mm, fmaxf(x0, x1));
            }
            mm = fmaxf(mm, __shfl_xor_sync(0xFFFFFFFFu, mm, 1));
            mm = fmaxf(mm, __shfl_xor_sync(0xFFFFFFFFu, mm, 2));
            Mred[row_l * 2 + wn] = mm;
        }
    }
    __syncthreads();

    #pragma unroll
    for (int mi = 0; mi < 2; ++mi) {
        #pragma unroll
        for (int h = 0; h < 2; ++h) {
            const int row_l = wm * 32 + mi * 16 + h * 8 + g;
            const int grow  = i0 + row_l;
            const float m = fmaxf(Mred[row_l * 2], Mred[row_l * 2 + 1]);
            float s = 0.0f;
            #pragma unroll
            for (int ni = 0; ni < 8; ++ni) {
                const float e0 = __expf(acc[mi][ni][2 * h]     - m);
                const float e1 = __expf(acc[mi][ni][2 * h + 1] - m);
                s += e0 + e1;
                const size_t idx =
                    ((size_t)bh * SQ + grow) * SQ + j0 + wn * 64 + ni * 8 + 2 * tig;
                *(__half2*)(g_E + idx) = __float22half2_rn(make_float2(e0, e1));
            }
            s += __shfl_xor_sync(0xFFFFFFFFu, s, 1);
            s += __shfl_xor_sync(0xFFFFFFFFu, s, 2);
            Sred[row_l * 2 + wn] = s;
        }
    }
    __syncthreads();

    if (wn == 0 && tig == 0) {
        #pragma unroll
        for (int mi = 0; mi < 2; ++mi)
            #pragma unroll
            for (int h = 0; h < 2; ++h) {
                const int row_l = wm * 32 + mi * 16 + h * 8 + g;
                const int grow  = i0 + row_l;
                const float m = fmaxf(Mred[row_l * 2], Mred[row_l * 2 + 1]);
                const float S = Sred[row_l * 2] + Sred[row_l * 2 + 1];
                g_MS[((size_t)bh * SQ + grow) * NTILE + blockIdx.x] =
                    make_float2(m, S);
            }
    }
}

// =====================================================================
// Kernel 2: combine per-tile stats -> per-(row, tile) factor f
// =====================================================================
__global__ __launch_bounds__(128)
void combine_kernel() {
    const size_t row = (size_t)blockIdx.x * 128 + threadIdx.x;
    const float4* mp = (const float4*)(g_MS + row * NTILE);
    float4 r[8];
    #pragma unroll
    for (int i = 0; i < 8; ++i) r[i] = mp[i];
    float M = r[0].x;
    #pragma unroll
    for (int i = 0; i < 8; ++i) { M = fmaxf(M, r[i].x); M = fmaxf(M, r[i].z); }
    float e[16], S = 0.0f;
    #pragma unroll
    for (int i = 0; i < 8; ++i) {
        e[2 * i]     = __expf(r[i].x - M); S += r[i].y * e[2 * i];
        e[2 * i + 1] = __expf(r[i].z - M); S += r[i].w * e[2 * i + 1];
    }
    const float inv = 1.0f / S;
    float4* f = (float4*)(g_F + row * NTILE);
    #pragma unroll
    for (int i = 0; i < 4; ++i)
        f[i] = make_float4(e[4 * i] * inv, e[4 * i + 1] * inv,
                           e[4 * i + 2] * inv, e[4 * i + 3] * inv);
}

// =====================================================================
// Kernel 3: context = attn @ V via fp16 tensor cores (A fp16 single
// from g_E, V fp16 hi/lo). Writes normalized fp32 attn (disjoint output
// buffer -> no aliasing) and fp32 ctx.
// =====================================================================
#define AVP 72
#define AVPW 36
#define AV_BK 64

__global__ __launch_bounds__(256, 2)
void av_kernel(float* __restrict__ attn, float* __restrict__ ctx) {
    extern __shared__ char smem[];
    __half* base = (__half*)smem;
    __half* As[2]  = { base, base + 128 * AVP };
    __half* vb = base + 2 * 128 * AVP;
    __half* VsH[2] = { vb,               vb + 2 * 64 * AVP };
    __half* VsL[2] = { vb + 64 * AVP,    vb + 3 * 64 * AVP };

    const int t   = threadIdx.x;
    const int bh  = blockIdx.y;
    const int i0  = blockIdx.x * 128;
    const int wid = t >> 5;
    const int lane = t & 31;
    const int wm  = wid >> 1;        // rows wm*32..+31
    const int wn  = wid & 1;         // cols wn*32..+31
    const int g   = lane >> 2;
    const int tig = lane & 3;

    const __half* Eg = g_E + ((size_t)bh * SQ + i0) * SQ;
    float* Ag32 = attn + ((size_t)bh * SQ + i0) * SQ;
    const __half* Vth = g_Vth + (size_t)bh * DH * SQ;
    const __half* Vtl = g_Vtl + (size_t)bh * DH * SQ;

    // load/proc mapping: 4 rows x 8 k per thread
    const int rg = (t >> 3) * 4;     // rows rg..rg+3
    const int kg = (t & 7) * 8;      // k cols kg..kg+7

    uint4 ra[4];                     // 8 fp16 e-values per row
    float fv[4];

    float acc[2][4][4];
    #pragma unroll
    for (int a = 0; a < 2; ++a)
        #pragma unroll
        for (int b = 0; b < 4; ++b)
            #pragma unroll
            for (int c = 0; c < 4; ++c) acc[a][b][c] = 0.0f;

    auto ldF = [&](int kt) {
        #pragma unroll
        for (int i = 0; i < 4; ++i)
            fv[i] = g_F[((size_t)bh * SQ + i0 + rg + i) * NTILE + kt];
    };
    auto ldA = [&](int n) {
        #pragma unroll
        for (int i = 0; i < 4; ++i)
            ra[i] = *(const uint4*)(Eg + (size_t)(rg + i) * SQ + n * AV_BK + kg);
    };
    auto ldV = [&](int n, int buf) {
        #pragma unroll
        for (int it = 0; it < 2; ++it) {
            const int id  = it * 256 + t;     // 0..511
            const int d   = id >> 3;
            const int seg = (id & 7) * 8;
            cpasync16(VsH[buf] + d * AVP + seg, Vth + (size_t)d * SQ + n * AV_BK + seg);
            cpasync16(VsL[buf] + d * AVP + seg, Vtl + (size_t)d * SQ + n * AV_BK + seg);
        }
        cp_commit();
    };
    auto procA = [&](int n, int buf) {
        #pragma unroll
        for (int i = 0; i < 4; ++i) {
            const int row = rg + i;
            const float f = fv[i];
            const __half2* hp = (const __half2*)&ra[i];
            float2 p0 = __half22float2(hp[0]);
            float2 p1 = __half22float2(hp[1]);
            float2 p2 = __half22float2(hp[2]);
            float2 p3 = __half22float2(hp[3]);
            p0.x *= f; p0.y *= f; p1.x *= f; p1.y *= f;
            p2.x *= f; p2.y *= f; p3.x *= f; p3.y *= f;
            float* p = Ag32 + (size_t)row * SQ + n * AV_BK + kg;
            *(float4*)p       = make_float4(p0.x, p0.y, p1.x, p1.y);
            *(float4*)(p + 4) = make_float4(p2.x, p2.y, p3.x, p3.y);
            uint4 w;
            *(__half2*)&w.x = __float22half2_rn(p0);
            *(__half2*)&w.y = __float22half2_rn(p1);
            *(__half2*)&w.z = __float22half2_rn(p2);
            *(__half2*)&w.w = __float22half2_rn(p3);
            *(uint4*)&As[buf][row * AVP + kg] = w;
        }
    };

    // ---- prologue: chunk 0 ----
    ldF(0);
    ldA(0);
    ldV(0, 0);
    procA(0, 0);
    cp_wait0();
    __syncthreads();

    // ---- main loop: 32 chunks of BK=64, ascending ----
    for (int c = 0; c < SQ / AV_BK; ++c) {
        const int cur = c & 1;
        if (c < SQ / AV_BK - 1) {
            const int n = c + 1;
            if ((n & 1) == 0) ldF(n >> 1);
            ldA(n);
            ldV(n, 1 - cur);
        }
        {
            const unsigned* A  = (const unsigned*)As[cur];
            const unsigned* VH = (const unsigned*)VsH[cur];
            const unsigned* VL = (const unsigned*)VsL[cur];
            #pragma unroll
            for (int ks = 0; ks < 4; ++ks) {
                unsigned a[2][4];
                #pragma unroll
                for (int mi = 0; mi < 2; ++mi) {
                    const int w = (wm * 32 + mi * 16 + g) * AVPW + 8 * ks + tig;
                    a[mi][0] = A[w];       a[mi][1] = A[w + 8 * AVPW];
                    a[mi][2] = A[w + 4];   a[mi][3] = A[w + 8 * AVPW + 4];
                }
                #pragma unroll
                for (int ni = 0; ni < 4; ++ni) {
                    const int wb = (wn * 32 + ni * 8 + g) * AVPW + 8 * ks + tig;
                    const unsigned bh0 = VH[wb], bh1 = VH[wb + 4];
                    const unsigned bl0 = VL[wb], bl1 = VL[wb + 4];
                    MMA_F16(acc[0][ni], a[0], bh0, bh1);
                    MMA_F16(acc[1][ni], a[1], bh0, bh1);
                    MMA_F16(acc[0][ni], a[0], bl0, bl1);
                    MMA_F16(acc[1][ni], a[1], bl0, bl1);
                }
            }
        }
        if (c < SQ / AV_BK - 1) {
            procA(c + 1, 1 - cur);
            cp_wait0();
        }
        __syncthreads();
    }

    // ---- epilogue: write context ----
    #pragma unroll
    for (int mi = 0; mi < 2; ++mi)
        #pragma unroll
        for (int ni = 0; ni < 4; ++ni)
            #pragma unroll
            for (int h = 0; h < 2; ++h) {
                const int row = i0 + wm * 32 + mi * 16 + h * 8 + g;
                const int col = wn * 32 + ni * 8 + 2 * tig;
                *(float2*)(ctx + ((size_t)bh * SQ + row) * DH + col) =
                    make_float2(acc[mi][ni][2 * h], acc[mi][ni][2 * h + 1]);
            }
}

// =====================================================================
extern "C" void kernel_launch(void* const* d_in, const int* in_sizes, int n_in,
                              void* d_out, int out_size) {
    const float* q = (const float*)d_in[0];
    const float* k = (const float*)d_in[1];
    const float* v = (const float*)d_in[2];
    const void*  mask = d_in[3];

    float* ctx  = (float*)d_out;                              // [24, 2048, 64]
    float* attn = (float*)d_out + (size_t)NBH * SQ * DH;      // [24, 2048, 2048]

    const int qk_smem = 4 * 128 * QP * 2 + 512 * 4;           // 75776
    cudaFuncSetAttribute(qk_scores_kernel,
                         cudaFuncAttributeMaxDynamicSharedMemorySize, qk_smem);
    const int av_smem = (2 * 128 * AVP + 4 * 64 * AVP) * 2;   // 73728
    cudaFuncSetAttribute(av_kernel,
                         cudaFuncAttributeMaxDynamicSharedMemorySize, av_smem);

    detect_mask_kernel<<<1, 32>>>((const unsigned char*)mask);

    dim3 gv(SQ / 64, NBH);
    vconv_kernel<<<gv, 256>>>(v);

    dim3 g1(SQ / 128, SQ / 128, NBH);
    qk_scores_kernel<<<g1, 256, qk_smem>>>(q, k, mask);

    combine_kernel<<<NBH * SQ / 128, 128>>>();

    dim3 g3(SQ / 128, NBH);
    av_kernel<<<g3, 256, av_smem>>>(attn, ctx);
}

// round 12
// speedup vs baseline: 2.1728x; 1.0846x over previous
#include <cuda_runtime.h>
#include <cuda_bf16.h>
#include <cuda_fp16.h>
#include <cstdint>

#define SQ 2048
#define DH 64
#define NBH 24
#define NTILE 16
#define MASKF (-1.0e9f)
#define SCL 0.5f

typedef unsigned long long ull;

// mask dtype flag: 0 = 1-byte bool/uint8, 1 = int32, 2 = float32
__device__ int g_mask_dtype;
// per-(row, 128-col tile) partial softmax stats (m_i, s_i)
__device__ float2 g_MS[(size_t)NBH * SQ * NTILE];
// per-(row, tile) rescale factor f = exp(m_i - M) / S
__device__ float g_F[(size_t)NBH * SQ * NTILE];
// V transposed to [bh][d][k], fp16
__device__ __half g_Vth[(size_t)NBH * DH * SQ];
// unnormalized softmax numerators e = exp(x - m_tile), fp16 (dedicated scratch)
__device__ __half g_E[(size_t)NBH * SQ * SQ];

// ---- cp.async helpers ----
__device__ __forceinline__ void cpasync16(const void* smem_dst, const void* gmem_src) {
    uint32_t d = (uint32_t)__cvta_generic_to_shared(smem_dst);
    asm volatile("cp.async.cg.shared.global [%0], [%1], 16;" :: "r"(d), "l"(gmem_src));
}
__device__ __forceinline__ void cp_commit() { asm volatile("cp.async.commit_group;"); }
__device__ __forceinline__ void cp_wait0()  { asm volatile("cp.async.wait_group 0;"); }

// ---- mma.sync macros ----
#define MMA_BF16(d, a, b0, b1)                                                  \
    asm volatile("mma.sync.aligned.m16n8k16.row.col.f32.bf16.bf16.f32 "         \
                 "{%0,%1,%2,%3}, {%4,%5,%6,%7}, {%8,%9}, {%0,%1,%2,%3};"        \
                 : "+f"((d)[0]), "+f"((d)[1]), "+f"((d)[2]), "+f"((d)[3])       \
                 : "r"((a)[0]), "r"((a)[1]), "r"((a)[2]), "r"((a)[3]),          \
                   "r"(b0), "r"(b1))

#define MMA_F16(d, a, b0, b1)                                                   \
    asm volatile("mma.sync.aligned.m16n8k16.row.col.f32.f16.f16.f32 "           \
                 "{%0,%1,%2,%3}, {%4,%5,%6,%7}, {%8,%9}, {%0,%1,%2,%3};"        \
                 : "+f"((d)[0]), "+f"((d)[1]), "+f"((d)[2]), "+f"((d)[3])       \
                 : "r"((a)[0]), "r"((a)[1]), "r"((a)[2]), "r"((a)[3]),          \
                   "r"(b0), "r"(b1))

__device__ __forceinline__ unsigned pkbf(float a, float b) {
    __nv_bfloat162 v;
    v.x = __float2bfloat16(a);
    v.y = __float2bfloat16(b);
    return *(unsigned*)&v;
}

// =====================================================================
// Kernel 0: detect mask dtype from its byte pattern (1 warp, 256 bytes)
// =====================================================================
__global__ void detect_mask_kernel(const unsigned char* __restrict__ m) {
    const int t = threadIdx.x;
    ull v = ((const ull*)m)[t];
    int ge2 = 0, off = 0;
    #pragma unroll
    for (int i = 0; i < 8; ++i) {
        unsigned char b = (unsigned char)((v >> (8 * i)) & 0xFF);
        const int j = t * 8 + i;
        if (b >= 2) ge2 = 1;
        if ((j & 3) && b) off = 1;
    }
    ge2 = __any_sync(0xFFFFFFFFu, ge2);
    off = __any_sync(0xFFFFFFFFu, off);
    if (t == 0) g_mask_dtype = ge2 ? 2 : (off ? 0 : 1);
}

// =====================================================================
// Kernel 0b: V -> transposed fp16 buffer Vt[d][k]
// =====================================================================
__global__ __launch_bounds__(256)
void vconv_kernel(const float* __restrict__ v) {
    __shared__ float s[64][65];
    const int bh = blockIdx.y;
    const int k0 = blockIdx.x * 64;
    const int t  = threadIdx.x;
    const float* Vg = v + ((size_t)bh * SQ + k0) * DH;
    {
        const int kk = t >> 2, dg = (t & 3) * 16;
        #pragma unroll
        for (int i = 0; i < 4; ++i) {
            float4 x = *(const float4*)(Vg + (size_t)kk * DH + dg + 4 * i);
            s[kk][dg + 4 * i + 0] = x.x; s[kk][dg + 4 * i + 1] = x.y;
            s[kk][dg + 4 * i + 2] = x.z; s[kk][dg + 4 * i + 3] = x.w;
        }
    }
    __syncthreads();
    {
        const int d = t >> 2, kg = (t & 3) * 16;
        __half hi[16];
        #pragma unroll
        for (int i = 0; i < 16; ++i)
            hi[i] = __float2half_rn(s[kg + i][d]);
        const size_t off = ((size_t)bh * DH + d) * SQ + k0 + kg;
        *(uint4*)&g_Vth[off]     = *(uint4*)hi;
        *(uint4*)&g_Vth[off + 8] = *(uint4*)(hi + 8);
    }
}

// =====================================================================
// Kernel 1: tensor-core QK^T via split-bf16 (3 products), fused
// scale+mask+tile-softmax. e-values stored fp16 -> g_E. 128x128, 8 warps.
// =====================================================================
#define QP 72          // bf16 row pitch
#define QPW 36         // pitch in 32-bit words

__global__ __launch_bounds__(256, 2)
void qk_scores_kernel(const float* __restrict__ q, const float* __restrict__ k,
                      const void* __restrict__ mask) {
    extern __shared__ char smem[];
    __nv_bfloat16* Qh = (__nv_bfloat16*)smem;
    __nv_bfloat16* Ql = Qh + 128 * QP;
    __nv_bfloat16* Kh = Ql + 128 * QP;
    __nv_bfloat16* Kl = Kh + 128 * QP;
    float* Mred = (float*)(smem + 4 * 128 * QP * 2);
    float* Sred = Mred + 256;

    const int t   = threadIdx.x;
    const int bh  = blockIdx.z;
    const int i0  = blockIdx.y * 128;
    const int j0  = blockIdx.x * 128;
    const int wid = t >> 5;
    const int lane = t & 31;
    const int wm  = wid >> 1;
    const int wn  = wid & 1;
    const int g   = lane >> 2;
    const int tig = lane & 3;

    const float* Qg = q + ((size_t)bh * SQ + i0) * DH;
    const float* Kg = k + ((size_t)bh * SQ + j0) * DH;

    #pragma unroll
    for (int i = 0; i < 8; ++i) {
        const int id  = t + 256 * i;
        const int row = id >> 4;
        const int c   = (id & 15) * 4;
        float4 x = *(const float4*)(Qg + row * DH + c);
        float h0 = __bfloat162float(__float2bfloat16(x.x));
        float h1 = __bfloat162float(__float2bfloat16(x.y));
        float h2 = __bfloat162float(__float2bfloat16(x.z));
        float h3 = __bfloat162float(__float2bfloat16(x.w));
        *(uint2*)&Qh[row * QP + c] = make_uint2(pkbf(h0, h1), pkbf(h2, h3));
        *(uint2*)&Ql[row * QP + c] =
            make_uint2(pkbf(x.x - h0, x.y - h1), pkbf(x.z - h2, x.w - h3));
        float4 y = *(const float4*)(Kg + row * DH + c);
        float k0 = __bfloat162float(__float2bfloat16(y.x));
        float k1 = __bfloat162float(__float2bfloat16(y.y));
        float k2 = __bfloat162float(__float2bfloat16(y.z));
        float k3 = __bfloat162float(__float2bfloat16(y.w));
        *(uint2*)&Kh[row * QP + c] = make_uint2(pkbf(k0, k1), pkbf(k2, k3));
        *(uint2*)&Kl[row * QP + c] =
            make_uint2(pkbf(y.x - k0, y.y - k1), pkbf(y.z - k2, y.w - k3));
    }
    __syncthreads();

    const unsigned* Qhu = (const unsigned*)Qh;
    const unsigned* Qlu = (const unsigned*)Ql;
    const unsigned* Khu = (const unsigned*)Kh;
    const unsigned* Klu = (const unsigned*)Kl;

    float acc[2][8][4];
    #pragma unroll
    for (int a = 0; a < 2; ++a)
        #pragma unroll
        for (int b = 0; b < 8; ++b)
            #pragma unroll
            for (int c = 0; c < 4; ++c) acc[a][b][c] = 0.0f;

    #pragma unroll
    for (int ks = 0; ks < 4; ++ks) {
        unsigned aH[2][4], aL[2][4];
        #pragma unroll
        for (int mi = 0; mi < 2; ++mi) {
            const int w = (wm * 32 + mi * 16 + g) * QPW + 8 * ks + tig;
            aH[mi][0] = Qhu[w];       aH[mi][1] = Qhu[w + 8 * QPW];
            aH[mi][2] = Qhu[w + 4];   aH[mi][3] = Qhu[w + 8 * QPW + 4];
            aL[mi][0] = Qlu[w];       aL[mi][1] = Qlu[w + 8 * QPW];
            aL[mi][2] = Qlu[w + 4];   aL[mi][3] = Qlu[w + 8 * QPW + 4];
        }
        #pragma unroll
        for (int ni = 0; ni < 8; ++ni) {
            const int wb = (wn * 64 + ni * 8 + g) * QPW + 8 * ks + tig;
            const unsigned bh0 = Khu[wb], bh1 = Khu[wb + 4];
            const unsigned bl0 = Klu[wb], bl1 = Klu[wb + 4];
            MMA_BF16(acc[0][ni], aH[0], bh0, bh1);
            MMA_BF16(acc[1][ni], aH[1], bh0, bh1);
            MMA_BF16(acc[0][ni], aL[0], bh0, bh1);
            MMA_BF16(acc[1][ni], aL[1], bh0, bh1);
            MMA_BF16(acc[0][ni], aH[0], bl0, bl1);
            MMA_BF16(acc[1][ni], aH[1], bl0, bl1);
        }
    }
    __syncthreads();

    const int mf = g_mask_dtype;

    #pragma unroll
    for (int mi = 0; mi < 2; ++mi) {
        #pragma unroll
        for (int h = 0; h < 2; ++h) {
            const int row_l = wm * 32 + mi * 16 + h * 8 + g;
            const int grow  = i0 + row_l;
            float mm = -3.0e38f;
            #pragma unroll
            for (int ni = 0; ni < 8; ++ni) {
                float& x0 = acc[mi][ni][2 * h];
                float& x1 = acc[mi][ni][2 * h + 1];
                x0 *= SCL; x1 *= SCL;
                const size_t idx =
                    ((size_t)bh * SQ + grow) * SQ + j0 + wn * 64 + ni * 8 + 2 * tig;
                if (mf == 0) {
                    uchar2 m = *(const uchar2*)((const unsigned char*)mask + idx);
                    if (m.x) x0 = MASKF; if (m.y) x1 = MASKF;
                } else if (mf == 1) {
                    int2 m = *(const int2*)((const int*)mask + idx);
                    if (m.x) x0 = MASKF; if (m.y) x1 = MASKF;
                } else {
                    float2 m = *(const float2*)((const float*)mask + idx);
                    if (m.x != 0.0f) x0 = MASKF; if (m.y != 0.0f) x1 = MASKF;
                }
                mm = fmaxf(mm, fmaxf(x0, x1));
            }
            mm = fmaxf(mm, __shfl_xor_sync(0xFFFFFFFFu, mm, 1));
            mm = fmaxf(mm, __shfl_xor_sync(0xFFFFFFFFu, mm, 2));
            Mred[row_l * 2 + wn] = mm;
        }
    }
    __syncthreads();

    #pragma unroll
    for (int mi = 0; mi < 2; ++mi) {
        #pragma unroll
        for (int h = 0; h < 2; ++h) {
            const int row_l = wm * 32 + mi * 16 + h * 8 + g;
            const int grow  = i0 + row_l;
            const float m = fmaxf(Mred[row_l * 2], Mred[row_l * 2 + 1]);
            float s = 0.0f;
            #pragma unroll
            for (int ni = 0; ni < 8; ++ni) {
                const float e0 = __expf(acc[mi][ni][2 * h]     - m);
                const float e1 = __expf(acc[mi][ni][2 * h + 1] - m);
                s += e0 + e1;
                const size_t idx =
                    ((size_t)bh * SQ + grow) * SQ + j0 + wn * 64 + ni * 8 + 2 * tig;
                *(__half2*)(g_E + idx) = __float22half2_rn(make_float2(e0, e1));
            }
            s += __shfl_xor_sync(0xFFFFFFFFu, s, 1);
            s += __shfl_xor_sync(0xFFFFFFFFu, s, 2);
            Sred[row_l * 2 + wn] = s;
        }
    }
    __syncthreads();

    if (wn == 0 && tig == 0) {
        #pragma unroll
        for (int mi = 0; mi < 2; ++mi)
            #pragma unroll
            for (int h = 0; h < 2; ++h) {
                const int row_l = wm * 32 + mi * 16 + h * 8 + g;
                const int grow  = i0 + row_l;
                const float m = fmaxf(Mred[row_l * 2], Mred[row_l * 2 + 1]);
                const float S = Sred[row_l * 2] + Sred[row_l * 2 + 1];
                g_MS[((size_t)bh * SQ + grow) * NTILE + blockIdx.x] =
                    make_float2(m, S);
            }
    }
}

// =====================================================================
// Kernel 2: combine per-tile stats -> per-(row, tile) factor f
// =====================================================================
__global__ __launch_bounds__(128)
void combine_kernel() {
    const size_t row = (size_t)blockIdx.x * 128 + threadIdx.x;
    const float4* mp = (const float4*)(g_MS + row * NTILE);
    float4 r[8];
    #pragma unroll
    for (int i = 0; i < 8; ++i) r[i] = mp[i];
    float M = r[0].x;
    #pragma unroll
    for (int i = 0; i < 8; ++i) { M = fmaxf(M, r[i].x); M = fmaxf(M, r[i].z); }
    float e[16], S = 0.0f;
    #pragma unroll
    for (int i = 0; i < 8; ++i) {
        e[2 * i]     = __expf(r[i].x - M); S += r[i].y * e[2 * i];
        e[2 * i + 1] = __expf(r[i].z - M); S += r[i].w * e[2 * i + 1];
    }
    const float inv = 1.0f / S;
    float4* f = (float4*)(g_F + row * NTILE);
    #pragma unroll
    for (int i = 0; i < 4; ++i)
        f[i] = make_float4(e[4 * i] * inv, e[4 * i + 1] * inv,
                           e[4 * i + 2] * inv, e[4 * i + 3] * inv);
}

// =====================================================================
// Kernel 3: context = attn @ V via fp16 tensor cores (A fp16 from g_E,
// V fp16 single product). Writes normalized fp32 attn + fp32 ctx.
// =====================================================================
#define AVP 72
#define AVPW 36
#define AV_BK 64

__global__ __launch_bounds__(256, 2)
void av_kernel(float* __restrict__ attn, float* __restrict__ ctx) {
    extern __shared__ char smem[];
    __half* base = (__half*)smem;
    __half* As[2]  = { base, base + 128 * AVP };
    __half* vb = base + 2 * 128 * AVP;
    __half* VsH[2] = { vb, vb + 64 * AVP };

    const int t   = threadIdx.x;
    const int bh  = blockIdx.y;
    const int i0  = blockIdx.x * 128;
    const int wid = t >> 5;
    const int lane = t & 31;
    const int wm  = wid >> 1;        // rows wm*32..+31
    const int wn  = wid & 1;         // cols wn*32..+31
    const int g   = lane >> 2;
    const int tig = lane & 3;

    const __half* Eg = g_E + ((size_t)bh * SQ + i0) * SQ;
    float* Ag32 = attn + ((size_t)bh * SQ + i0) * SQ;
    const __half* Vth = g_Vth + (size_t)bh * DH * SQ;

    const int rg = (t >> 3) * 4;     // rows rg..rg+3
    const int kg = (t & 7) * 8;      // k cols kg..kg+7

    uint4 ra[4];
    float fv[4];

    float acc[2][4][4];
    #pragma unroll
    for (int a = 0; a < 2; ++a)
        #pragma unroll
        for (int b = 0; b < 4; ++b)
            #pragma unroll
            for (int c = 0; c < 4; ++c) acc[a][b][c] = 0.0f;

    auto ldF = [&](int kt) {
        #pragma unroll
        for (int i = 0; i < 4; ++i)
            fv[i] = g_F[((size_t)bh * SQ + i0 + rg + i) * NTILE + kt];
    };
    auto ldA = [&](int n) {
        #pragma unroll
        for (int i = 0; i < 4; ++i)
            ra[i] = *(const uint4*)(Eg + (size_t)(rg + i) * SQ + n * AV_BK + kg);
    };
    auto ldV = [&](int n, int buf) {
        #pragma unroll
        for (int it = 0; it < 2; ++it) {
            const int id  = it * 256 + t;
            const int d   = id >> 3;
            const int seg = (id & 7) * 8;
            cpasync16(VsH[buf] + d * AVP + seg, Vth + (size_t)d * SQ + n * AV_BK + seg);
        }
        cp_commit();
    };
    auto procA = [&](int n, int buf) {
        #pragma unroll
        for (int i = 0; i < 4; ++i) {
            const int row = rg + i;
            const float f = fv[i];
            const __half2* hp = (const __half2*)&ra[i];
            float2 p0 = __half22float2(hp[0]);
            float2 p1 = __half22float2(hp[1]);
            float2 p2 = __half22float2(hp[2]);
            float2 p3 = __half22float2(hp[3]);
            p0.x *= f; p0.y *= f; p1.x *= f; p1.y *= f;
            p2.x *= f; p2.y *= f; p3.x *= f; p3.y *= f;
            float* p = Ag32 + (size_t)row * SQ + n * AV_BK + kg;
            *(float4*)p       = make_float4(p0.x, p0.y, p1.x, p1.y);
            *(float4*)(p + 4) = make_float4(p2.x, p2.y, p3.x, p3.y);
            uint4 w;
            *(__half2*)&w.x = __float22half2_rn(p0);
            *(__half2*)&w.y = __float22half2_rn(p1);
            *(__half2*)&w.z = __float22half2_rn(p2);
            *(__half2*)&w.w = __float22half2_rn(p3);
            *(uint4*)&As[buf][row * AVP + kg] = w;
        }
    };

    ldF(0);
    ldA(0);
    ldV(0, 0);
    procA(0, 0);
    cp_wait0();
    __syncthreads();

    for (int c = 0; c < SQ / AV_BK; ++c) {
        const int cur = c & 1;
        if (c < SQ / AV_BK - 1) {
            const int n = c + 1;
            if ((n & 1) == 0) ldF(n >> 1);
            ldA(n);
            ldV(n, 1 - cur);
        }
        {
            const unsigned* A  = (const unsigned*)As[cur];
            const unsigned* VH = (const unsigned*)VsH[cur];
            #pragma unroll
            for (int ks = 0; ks < 4; ++ks) {
                unsigned a[2][4];
                #pragma unroll
                for (int mi = 0; mi < 2; ++mi) {
                    const int w = (wm * 32 + mi * 16 + g) * AVPW + 8 * ks + tig;
                    a[mi][0] = A[w];       a[mi][1] = A[w + 8 * AVPW];
                    a[mi][2] = A[w + 4];   a[mi][3] = A[w + 8 * AVPW + 4];
                }
                #pragma unroll
                for (int ni = 0; ni < 4; ++ni) {
                    const int wb = (wn * 32 + ni * 8 + g) * AVPW + 8 * ks + tig;
                    const unsigned bh0 = VH[wb], bh1 = VH[wb + 4];
                    MMA_F16(acc[0][ni], a[0], bh0, bh1);
                    MMA_F16(acc[1][ni], a[1], bh0, bh1);
                }
            }
        }
        if (c < SQ / AV_BK - 1) {
            procA(c + 1, 1 - cur);
            cp_wait0();
        }
        __syncthreads();
    }

    #pragma unroll
    for (int mi = 0; mi < 2; ++mi)
        #pragma unroll
        for (int ni = 0; ni < 4; ++ni)
            #pragma unroll
            for (int h = 0; h < 2; ++h) {
                const int row = i0 + wm * 32 + mi * 16 + h * 8 + g;
                const int col = wn * 32 + ni * 8 + 2 * tig;
                *(float2*)(ctx + ((size_t)bh * SQ + row) * DH + col) =
                    make_float2(acc[mi][ni][2 * h], acc[mi][ni][2 * h + 1]);
            }
}

// =====================================================================
extern "C" void kernel_launch(void* const* d_in, const int* in_sizes, int n_in,
                              void* d_out, int out_size) {
    const float* q = (const float*)d_in[0];
    const float* k = (const float*)d_in[1];
    const float* v = (const float*)d_in[2];
    const void*  mask = d_in[3];

    float* ctx  = (float*)d_out;                              // [24, 2048, 64]
    float* attn = (float*)d_out + (size_t)NBH * SQ * DH;      // [24, 2048, 2048]

    const int qk_smem = 4 * 128 * QP * 2 + 512 * 4;           // 75776
    cudaFuncSetAttribute(qk_scores_kernel,
                         cudaFuncAttributeMaxDynamicSharedMemorySize, qk_smem);
    const int av_smem = (2 * 128 * AVP + 2 * 64 * AVP) * 2;   // 55296
    cudaFuncSetAttribute(av_kernel,
                         cudaFuncAttributeMaxDynamicSharedMemorySize, av_smem);

    detect_mask_kernel<<<1, 32>>>((const unsigned char*)mask);

    dim3 gv(SQ / 64, NBH);
    vconv_kernel<<<gv, 256>>>(v);

    dim3 g1(SQ / 128, SQ / 128, NBH);
    qk_scores_kernel<<<g1, 256, qk_smem>>>(q, k, mask);

    combine_kernel<<<NBH * SQ / 128, 128>>>();

    dim3 g3(SQ / 128, NBH);
    av_kernel<<<g3, 256, av_smem>>>(attn, ctx);
}